// round 7
// baseline (speedup 1.0000x reference)
#include <cuda_runtime.h>
#include <cuda_bf16.h>
#include <math.h>
#include <stdint.h>

#define NB 2
#define NC 8
#define NF 1024
#define NW 512
#define NHEAD 8
#define NHD 128
#define NBC (NB*NC)
#define TENS ((size_t)NB*NC*NF*NW)          // 8388608
#define WSZ  ((size_t)NC*NF*NF)             // 8388608 per weight tensor

// ---------------- scratch (static device globals; no runtime alloc) ----------------
__device__ __align__(16) __nv_bfloat16 g_cqh[TENS], g_cql[TENS];
__device__ __align__(16) __nv_bfloat16 g_ckh[TENS], g_ckl[TENS];
__device__ __align__(16) __nv_bfloat16 g_cvh[TENS], g_cvl[TENS];
__device__ __align__(16) __nv_bfloat16 g_qh[TENS], g_ql[TENS];
__device__ __align__(16) __nv_bfloat16 g_kh[TENS], g_kl[TENS];
__device__ __align__(16) __nv_bfloat16 g_ah[TENS], g_al[TENS];
__device__ __align__(16) __nv_bfloat16 g_wh[4*WSZ], g_wl[4*WSZ];
__device__ __align__(16) float g_q[TENS], g_k[TENS], g_v[TENS];

// ---------------- helpers ----------------
__device__ __forceinline__ void split_bf16(float x, __nv_bfloat16& h, __nv_bfloat16& l) {
    h = __float2bfloat16(x);
    l = __float2bfloat16(x - __bfloat162float(h));
}
__device__ __forceinline__ uint32_t smem_u32(const void* p) {
    return (uint32_t)__cvta_generic_to_shared(p);
}
__device__ __forceinline__ void cp16(uint32_t dst, const void* src) {
    asm volatile("cp.async.cg.shared.global [%0], [%1], 16;" :: "r"(dst), "l"(src));
}
__device__ __forceinline__ void cp_commit() { asm volatile("cp.async.commit_group;"); }
template<int N> __device__ __forceinline__ void cp_wait() {
    asm volatile("cp.async.wait_group %0;" :: "n"(N));
}
__device__ __forceinline__ void ldsm4(uint32_t r[4], uint32_t addr) {
    asm volatile("ldmatrix.sync.aligned.m8n8.x4.shared.b16 {%0,%1,%2,%3},[%4];"
                 : "=r"(r[0]), "=r"(r[1]), "=r"(r[2]), "=r"(r[3]) : "r"(addr));
}
__device__ __forceinline__ void ldsm4t(uint32_t r[4], uint32_t addr) {
    asm volatile("ldmatrix.sync.aligned.m8n8.x4.trans.shared.b16 {%0,%1,%2,%3},[%4];"
                 : "=r"(r[0]), "=r"(r[1]), "=r"(r[2]), "=r"(r[3]) : "r"(addr));
}
__device__ __forceinline__ void mma16816(float c[4], const uint32_t a[4], uint32_t b0, uint32_t b1) {
    asm volatile("mma.sync.aligned.m16n8k16.row.col.f32.bf16.bf16.f32 "
                 "{%0,%1,%2,%3},{%4,%5,%6,%7},{%8,%9},{%0,%1,%2,%3};"
                 : "+f"(c[0]), "+f"(c[1]), "+f"(c[2]), "+f"(c[3])
                 : "r"(a[0]), "r"(a[1]), "r"(a[2]), "r"(a[3]), "r"(b0), "r"(b1));
}

// ---------------- fused 3x conv2d (3x3, pad 1, C=8 in/out) -> bf16 hi/lo ----------------
__global__ void __launch_bounds__(256) conv3_kernel(
    const float* __restrict__ x,
    const float* __restrict__ wq, const float* __restrict__ bq,
    const float* __restrict__ wk, const float* __restrict__ bk,
    const float* __restrict__ wv, const float* __restrict__ bv)
{
    __shared__ float xs[NC][34][36];
    __shared__ float ws[3*NC*NC*9];
    int tid = threadIdx.x;
    int bxo = blockIdx.x * 32;
    int byo = blockIdx.y * 32;
    int b   = blockIdx.z;

    for (int i = tid; i < NC*NC*9; i += 256) {
        ws[i]             = wq[i];
        ws[NC*NC*9 + i]   = wk[i];
        ws[2*NC*NC*9 + i] = wv[i];
    }
    for (int i = tid; i < NC*34*34; i += 256) {
        int ci = i / (34*34);
        int r  = (i / 34) % 34;
        int cl = i % 34;
        int gy = byo + r - 1, gx = bxo + cl - 1;
        float v = 0.f;
        if (gy >= 0 && gy < NF && gx >= 0 && gx < NW)
            v = x[(((size_t)b*NC + ci)*NF + gy)*NW + gx];
        xs[ci][r][cl] = v;
    }
    __syncthreads();

    #pragma unroll
    for (int p = 0; p < 4; ++p) {
        int pid = tid + p*256;
        int py = pid >> 5, px = pid & 31;
        float aq[NC], ak[NC], av[NC];
        #pragma unroll
        for (int co = 0; co < NC; ++co) { aq[co]=bq[co]; ak[co]=bk[co]; av[co]=bv[co]; }
        #pragma unroll
        for (int ci = 0; ci < NC; ++ci) {
            float w9[9];
            #pragma unroll
            for (int dy = 0; dy < 3; ++dy)
                #pragma unroll
                for (int dx = 0; dx < 3; ++dx)
                    w9[dy*3+dx] = xs[ci][py+dy][px+dx];
            #pragma unroll
            for (int co = 0; co < NC; ++co) {
                int wb = (co*NC + ci)*9;
                float sq=0.f, sk=0.f, sv=0.f;
                #pragma unroll
                for (int t = 0; t < 9; ++t) {
                    sq += w9[t]*ws[wb+t];
                    sk += w9[t]*ws[NC*NC*9 + wb+t];
                    sv += w9[t]*ws[2*NC*NC*9 + wb+t];
                }
                aq[co]+=sq; ak[co]+=sk; av[co]+=sv;
            }
        }
        int gy = byo + py, gx = bxo + px;
        #pragma unroll
        for (int co = 0; co < NC; ++co) {
            size_t o = (((size_t)b*NC+co)*NF + gy)*NW + gx;
            __nv_bfloat16 h, l;
            split_bf16(aq[co], h, l); g_cqh[o]=h; g_cql[o]=l;
            split_bf16(ak[co], h, l); g_ckh[o]=h; g_ckl[o]=l;
            split_bf16(av[co], h, l); g_cvh[o]=h; g_cvl[o]=l;
        }
    }
}

// ---------------- weight conversion: 4x (8,1024,1024) fp32 -> bf16 hi/lo ----------------
__global__ void __launch_bounds__(256) wconvert_kernel(
    const float* __restrict__ w0, const float* __restrict__ w1,
    const float* __restrict__ w2, const float* __restrict__ w3)
{
    size_t i = (size_t)blockIdx.x * blockDim.x + threadIdx.x;
    if (i >= WSZ) return;
    __nv_bfloat16 h, l;
    split_bf16(w0[i], h, l); g_wh[i]         = h; g_wl[i]         = l;
    split_bf16(w1[i], h, l); g_wh[WSZ + i]   = h; g_wl[WSZ + i]   = l;
    split_bf16(w2[i], h, l); g_wh[2*WSZ + i] = h; g_wl[2*WSZ + i] = l;
    split_bf16(w3[i], h, l); g_wh[3*WSZ + i] = h; g_wl[3*WSZ + i] = l;
}

// ---------------- mc_linear batched GEMM via bf16 tensor cores (3x split) ----------------
// C[z][m][n] = sum_k W[z%8][m][k] * B[z][k][n]; M=1024 N=512 K=1024
// CTA 128x128, BK=32, 3-stage cp.async pipeline (1 sync/iter), 8 warps, warp tile 32x64.
#define SA_ (128*40)
#define SB_ (32*136)
__global__ void __launch_bounds__(256, 2) gemm_mma(int wsel, int bsel, float* __restrict__ Cext)
{
    extern __shared__ __nv_bfloat16 sm_[];
    __nv_bfloat16* sAh = sm_;
    __nv_bfloat16* sAl = sAh + 3*SA_;
    __nv_bfloat16* sBh = sAl + 3*SA_;
    __nv_bfloat16* sBl = sBh + 3*SB_;

    int z = blockIdx.z;
    const __nv_bfloat16* Ah = g_wh + (size_t)wsel*WSZ + (size_t)(z & 7)*NF*NF;
    const __nv_bfloat16* Al = g_wl + (size_t)wsel*WSZ + (size_t)(z & 7)*NF*NF;
    const __nv_bfloat16 *BhG, *BlG;
    switch (bsel) {
        case 0:  BhG = g_cqh; BlG = g_cql; break;
        case 1:  BhG = g_ckh; BlG = g_ckl; break;
        case 2:  BhG = g_cvh; BlG = g_cvl; break;
        default: BhG = g_ah;  BlG = g_al;  break;
    }
    const __nv_bfloat16* Bh = BhG + (size_t)z*NF*NW;
    const __nv_bfloat16* Bl = BlG + (size_t)z*NF*NW;
    float* C = (bsel == 0 ? g_q : bsel == 1 ? g_k : bsel == 2 ? g_v : Cext) + (size_t)z*NF*NW;

    int m0 = blockIdx.y*128, n0 = blockIdx.x*128;
    int tid = threadIdx.x;
    int lane = tid & 31, wrp = tid >> 5;
    int wm = (wrp >> 1)*32, wn = (wrp & 1)*64;

    int arow = tid >> 1, acol = (tid & 1)*16;
    int brow = tid >> 3, bcol = (tid & 7)*8;

    float acc[2][8][4];
    #pragma unroll
    for (int i = 0; i < 2; ++i)
        #pragma unroll
        for (int j = 0; j < 8; ++j)
            #pragma unroll
            for (int t = 0; t < 4; ++t) acc[i][j][t] = 0.f;

    auto load_stage = [&](int s, int k0) {
        {
            const __nv_bfloat16* gh = Ah + (size_t)(m0 + arow)*NF + k0 + acol;
            const __nv_bfloat16* gl = Al + (size_t)(m0 + arow)*NF + k0 + acol;
            uint32_t dh = smem_u32(sAh + s*SA_ + arow*40 + acol);
            uint32_t dl = smem_u32(sAl + s*SA_ + arow*40 + acol);
            cp16(dh, gh); cp16(dh+16, gh+8);
            cp16(dl, gl); cp16(dl+16, gl+8);
        }
        {
            const __nv_bfloat16* gh = Bh + (size_t)(k0 + brow)*NW + n0 + bcol;
            const __nv_bfloat16* gl = Bl + (size_t)(k0 + brow)*NW + n0 + bcol;
            uint32_t dh = smem_u32(sBh + s*SB_ + brow*136 + bcol);
            uint32_t dl = smem_u32(sBl + s*SB_ + brow*136 + bcol);
            cp16(dh, gh); cp16(dh+128, gh+64);
            cp16(dl, gl); cp16(dl+128, gl+64);
        }
    };

    load_stage(0, 0);  cp_commit();
    load_stage(1, 32); cp_commit();
    const int KT = NF/32;
    for (int kt = 0; kt < KT; ++kt) {
        if (kt + 1 < KT) cp_wait<1>(); else cp_wait<0>();
        __syncthreads();
        if (kt + 2 < KT) { load_stage((kt+2)%3, (kt+2)*32); cp_commit(); }
        int s = kt % 3;
        const __nv_bfloat16* cAh = sAh + s*SA_;
        const __nv_bfloat16* cAl = sAl + s*SA_;
        const __nv_bfloat16* cBh = sBh + s*SB_;
        const __nv_bfloat16* cBl = sBl + s*SB_;
        #pragma unroll
        for (int ks = 0; ks < 32; ks += 16) {
            uint32_t ahf[2][4], alf[2][4];
            #pragma unroll
            for (int mt = 0; mt < 2; ++mt) {
                int roff = (wm + mt*16 + (lane & 15))*40 + ks + ((lane >> 4) << 3);
                ldsm4(ahf[mt], smem_u32(cAh + roff));
                ldsm4(alf[mt], smem_u32(cAl + roff));
            }
            #pragma unroll
            for (int p = 0; p < 4; ++p) {
                uint32_t bhf[4], blf[4];
                int boff = (ks + (lane & 15))*136 + wn + p*16 + ((lane >> 4) << 3);
                ldsm4t(bhf, smem_u32(cBh + boff));
                ldsm4t(blf, smem_u32(cBl + boff));
                #pragma unroll
                for (int mt = 0; mt < 2; ++mt) {
                    mma16816(acc[mt][2*p],   ahf[mt], bhf[0], bhf[1]);
                    mma16816(acc[mt][2*p],   ahf[mt], blf[0], blf[1]);
                    mma16816(acc[mt][2*p],   alf[mt], bhf[0], bhf[1]);
                    mma16816(acc[mt][2*p+1], ahf[mt], bhf[2], bhf[3]);
                    mma16816(acc[mt][2*p+1], ahf[mt], blf[2], blf[3]);
                    mma16816(acc[mt][2*p+1], alf[mt], bhf[2], bhf[3]);
                }
            }
        }
    }

    #pragma unroll
    for (int mt = 0; mt < 2; ++mt)
        #pragma unroll
        for (int nt = 0; nt < 8; ++nt) {
            int r = m0 + wm + mt*16 + (lane >> 2);
            int c = n0 + wn + nt*8 + (lane & 3)*2;
            *(float2*)&C[(size_t)r*NW + c]     = make_float2(acc[mt][nt][0], acc[mt][nt][1]);
            *(float2*)&C[(size_t)(r+8)*NW + c] = make_float2(acc[mt][nt][2], acc[mt][nt][3]);
        }
}

// ---------------- rotary on g_q/g_k (fp32 in) -> bf16 hi/lo out ----------------
__global__ void __launch_bounds__(256) rotary_kernel()
{
    size_t idx = (size_t)blockIdx.x * blockDim.x + threadIdx.x;
    if (idx >= TENS/2) return;
    int w    = (int)(idx % NW);
    size_t t = idx / NW;
    int fp = (int)(t % (NF/2));
    int bc = (int)(t / (NF/2));
    int f  = fp * 2;
    int d  = f & (NHD - 1);
    float inv = exp2f((float)d * (-13.287712379549449f / 128.0f));
    float th  = (float)w * inv;
    float sn, cs;
    sincosf(th, &sn, &cs);
    size_t i0 = ((size_t)bc*NF + f)*NW + w;
    size_t i1 = i0 + NW;
    __nv_bfloat16 h, l;
    float x1 = g_q[i0], x2 = g_q[i1];
    float r0 = x1*cs - x2*sn, r1 = x2*cs + x1*sn;
    split_bf16(r0, h, l); g_qh[i0]=h; g_ql[i0]=l;
    split_bf16(r1, h, l); g_qh[i1]=h; g_ql[i1]=l;
    x1 = g_k[i0]; x2 = g_k[i1];
    r0 = x1*cs - x2*sn; r1 = x2*cs + x1*sn;
    split_bf16(r0, h, l); g_kh[i0]=h; g_kl[i0]=l;
    split_bf16(r1, h, l); g_kh[i1]=h; g_kl[i1]=l;
}

// ---------------- QK^T logits via tensor cores: S = Q^T K / 32 + prev ----------------
__global__ void __launch_bounds__(256, 2) qk_mma(
    const float* __restrict__ prev, float* __restrict__ qkout)
{
    extern __shared__ __nv_bfloat16 sm_[];
    __nv_bfloat16* sAh = sm_;
    __nv_bfloat16* sAl = sAh + 2*SB_;
    __nv_bfloat16* sBh = sAl + 2*SB_;
    __nv_bfloat16* sBl = sBh + 2*SB_;

    int hz = blockIdx.z;
    int bc = hz >> 3, hd = hz & 7;
    size_t slab = ((size_t)bc*NF + hd*NHD)*NW;
    const __nv_bfloat16* QhG = g_qh + slab;
    const __nv_bfloat16* QlG = g_ql + slab;
    const __nv_bfloat16* KhG = g_kh + slab;
    const __nv_bfloat16* KlG = g_kl + slab;

    int m0 = blockIdx.y*128, n0 = blockIdx.x*128;
    int tid = threadIdx.x;
    int lane = tid & 31, wrp = tid >> 5;
    int wm = (wrp >> 1)*32, wn = (wrp & 1)*64;

    int lrow = tid >> 3, lcol = (tid & 7)*8;

    float acc[2][8][4];
    #pragma unroll
    for (int i = 0; i < 2; ++i)
        #pragma unroll
        for (int j = 0; j < 8; ++j)
            #pragma unroll
            for (int t = 0; t < 4; ++t) acc[i][j][t] = 0.f;

    auto load_stage = [&](int s, int k0) {
        size_t grow = (size_t)(k0 + lrow)*NW;
        {
            const __nv_bfloat16* gh = QhG + grow + m0 + lcol;
            const __nv_bfloat16* gl = QlG + grow + m0 + lcol;
            uint32_t dh = smem_u32(sAh + s*SB_ + lrow*136 + lcol);
            uint32_t dl = smem_u32(sAl + s*SB_ + lrow*136 + lcol);
            cp16(dh, gh); cp16(dh+128, gh+64);
            cp16(dl, gl); cp16(dl+128, gl+64);
        }
        {
            const __nv_bfloat16* gh = KhG + grow + n0 + lcol;
            const __nv_bfloat16* gl = KlG + grow + n0 + lcol;
            uint32_t dh = smem_u32(sBh + s*SB_ + lrow*136 + lcol);
            uint32_t dl = smem_u32(sBl + s*SB_ + lrow*136 + lcol);
            cp16(dh, gh); cp16(dh+128, gh+64);
            cp16(dl, gl); cp16(dl+128, gl+64);
        }
    };

    load_stage(0, 0);
    cp_commit();
    const int KT = NHD/32;   // 4
    for (int kt = 0; kt < KT; ++kt) {
        if (kt + 1 < KT) { load_stage((kt+1)&1, (kt+1)*32); cp_commit(); cp_wait<1>(); }
        else             { cp_wait<0>(); }
        __syncthreads();
        int s = kt & 1;
        const __nv_bfloat16* cAh = sAh + s*SB_;
        const __nv_bfloat16* cAl = sAl + s*SB_;
        const __nv_bfloat16* cBh = sBh + s*SB_;
        const __nv_bfloat16* cBl = sBl + s*SB_;
        #pragma unroll
        for (int ks = 0; ks < 32; ks += 16) {
            uint32_t ahf[2][4], alf[2][4];
            #pragma unroll
            for (int mt = 0; mt < 2; ++mt) {
                int off = (ks + (lane & 7) + ((lane >> 4) << 3))*136
                        + wm + mt*16 + (((lane >> 3) & 1) << 3);
                ldsm4t(ahf[mt], smem_u32(cAh + off));
                ldsm4t(alf[mt], smem_u32(cAl + off));
            }
            #pragma unroll
            for (int p = 0; p < 4; ++p) {
                uint32_t bhf[4], blf[4];
                int boff = (ks + (lane & 15))*136 + wn + p*16 + ((lane >> 4) << 3);
                ldsm4t(bhf, smem_u32(cBh + boff));
                ldsm4t(blf, smem_u32(cBl + boff));
                #pragma unroll
                for (int mt = 0; mt < 2; ++mt) {
                    mma16816(acc[mt][2*p],   ahf[mt], bhf[0], bhf[1]);
                    mma16816(acc[mt][2*p],   ahf[mt], blf[0], blf[1]);
                    mma16816(acc[mt][2*p],   alf[mt], bhf[0], bhf[1]);
                    mma16816(acc[mt][2*p+1], ahf[mt], bhf[2], bhf[3]);
                    mma16816(acc[mt][2*p+1], ahf[mt], blf[2], blf[3]);
                    mma16816(acc[mt][2*p+1], alf[mt], bhf[2], bhf[3]);
                }
            }
        }
        __syncthreads();
    }

    const float scale = 1.0f / 32.0f;   // 1/sqrt(F)
    size_t base = (size_t)hz * NW * NW;
    #pragma unroll
    for (int mt = 0; mt < 2; ++mt)
        #pragma unroll
        for (int nt = 0; nt < 8; ++nt) {
            int r = m0 + wm + mt*16 + (lane >> 2);
            int c = n0 + wn + nt*8 + (lane & 3)*2;
            size_t o0 = base + (size_t)r*NW + c;
            size_t o1 = base + (size_t)(r+8)*NW + c;
            float2 p0 = *(const float2*)&prev[o0];
            float2 p1 = *(const float2*)&prev[o1];
            *(float2*)&qkout[o0] = make_float2(acc[mt][nt][0]*scale + p0.x,
                                               acc[mt][nt][1]*scale + p0.y);
            *(float2*)&qkout[o1] = make_float2(acc[mt][nt][2]*scale + p1.x,
                                               acc[mt][nt][3]*scale + p1.y);
        }
}

// ---------------- softmax(S) @ V on tensor cores (gemm-proven patterns only) ----------------
// CTA = (32 q-rows, head). P chunked like gemm A tiles: 16 chunks x [32 rows][pitch 40].
// V fp32 [d][w] -> per-chunk LDG to regs, split, STS into [kw 32][pitch 136] (gemm B layout),
// consumed with gemm's trans-ldsm B index. 3-term split MMA. One sync per chunk.
#define PCH (32*40)       // one P chunk: 1280 elements
#define VBUF (32*136)     // one V buffer: 4352 elements
__global__ void __launch_bounds__(256) softmax_pv_mma(const float* __restrict__ qk)
{
    extern __shared__ __nv_bfloat16 pv_[];
    __nv_bfloat16* sPh = pv_;                 // 16*PCH
    __nv_bfloat16* sPl = sPh + 16*PCH;        // 16*PCH
    __nv_bfloat16* sV  = sPl + 16*PCH;        // 2 stages x (hi|lo) x VBUF
    __shared__ float linv[32];

    int hz  = blockIdx.y;
    int qt  = blockIdx.x;
    int bc  = hz >> 3, hd = hz & 7;
    int qw0 = qt * 32;
    size_t slab = ((size_t)bc*NF + hd*NHD)*NW;
    const float* S = qk + ((size_t)hz * NW + qw0) * NW;
    const float* V = g_v + slab;

    int tid = threadIdx.x;
    int lane = tid & 31, wrp = tid >> 5;

    // V chunk staging: 4 float4 per thread; u = tid + rep*256: d = u>>3, quad = u&7
    float vreg[16];
    auto load_v_regs = [&](int kw0) {
        #pragma unroll
        for (int rep = 0; rep < 4; ++rep) {
            int u = tid + rep*256;
            int d = u >> 3, quad = u & 7;
            *(float4*)&vreg[rep*4] = *(const float4*)&V[(size_t)d*NW + kw0 + quad*4];
        }
    };
    auto store_v_smem = [&](int stage) {
        __nv_bfloat16* bh = sV + stage*2*VBUF;
        __nv_bfloat16* bl = bh + VBUF;
        #pragma unroll
        for (int rep = 0; rep < 4; ++rep) {
            int u = tid + rep*256;
            int d = u >> 3, quad = u & 7;
            #pragma unroll
            for (int j = 0; j < 4; ++j) {
                __nv_bfloat16 h, l;
                split_bf16(vreg[rep*4 + j], h, l);
                bh[(quad*4 + j)*136 + d] = h;
                bl[(quad*4 + j)*136 + d] = l;
            }
        }
    };

    load_v_regs(0);   // overlap LDG with softmax below

    // softmax: warp w handles rows w*4 .. w*4+3; one global read, exp in regs
    #pragma unroll
    for (int j = 0; j < 4; ++j) {
        int row = wrp*4 + j;
        const float* Sr = S + (size_t)row*NW;
        float v[16];
        #pragma unroll
        for (int i = 0; i < 4; ++i)
            *(float4*)&v[i*4] = *(const float4*)&Sr[i*128 + lane*4];
        float m = v[0];
        #pragma unroll
        for (int i = 1; i < 16; ++i) m = fmaxf(m, v[i]);
        #pragma unroll
        for (int o = 16; o; o >>= 1) m = fmaxf(m, __shfl_xor_sync(0xffffffffu, m, o));
        float s = 0.f;
        #pragma unroll
        for (int i = 0; i < 16; ++i) { v[i] = __expf(v[i] - m); s += v[i]; }
        #pragma unroll
        for (int o = 16; o; o >>= 1) s += __shfl_xor_sync(0xffffffffu, s, o);
        if (lane == 0) linv[row] = 1.f / s;
        // store P into chunked layout: col = i*128 + lane*4 + t -> chunk i*4+(lane>>3), k=(lane&7)*4+t
        #pragma unroll
        for (int i = 0; i < 4; ++i) {
            int ch = i*4 + (lane >> 3);
            int kb = (lane & 7)*4;
            int base = ch*PCH + row*40 + kb;
            __nv_bfloat16 h0,l0,h1,l1,h2,l2,h3,l3;
            split_bf16(v[i*4+0], h0, l0); split_bf16(v[i*4+1], h1, l1);
            split_bf16(v[i*4+2], h2, l2); split_bf16(v[i*4+3], h3, l3);
            *(__nv_bfloat162*)&sPh[base]     = __nv_bfloat162(h0, h1);
            *(__nv_bfloat162*)&sPh[base + 2] = __nv_bfloat162(h2, h3);
            *(__nv_bfloat162*)&sPl[base]     = __nv_bfloat162(l0, l1);
            *(__nv_bfloat162*)&sPl[base + 2] = __nv_bfloat162(l2, l3);
        }
    }
    store_v_smem(0);
    __syncthreads();

    // MMA: 8 warps, warp tile m16 x n32: wm in {0,16}, wn in {0,32,64,96}
    int wm = (wrp >> 2)*16;
    int wn = (wrp & 3)*32;
    float acc[4][4];
    #pragma unroll
    for (int f = 0; f < 4; ++f)
        #pragma unroll
        for (int t = 0; t < 4; ++t) acc[f][t] = 0.f;

    for (int c = 0; c < 16; ++c) {
        if (c + 1 < 16) load_v_regs((c+1)*32);
        const __nv_bfloat16* cVh = sV + (c & 1)*2*VBUF;
        const __nv_bfloat16* cVl = cVh + VBUF;
        const __nv_bfloat16* cPh = sPh + c*PCH;
        const __nv_bfloat16* cPl = sPl + c*PCH;
        #pragma unroll
        for (int ks = 0; ks < 32; ks += 16) {
            uint32_t ah[4], al[4];
            int roff = (wm + (lane & 15))*40 + ks + ((lane >> 4) << 3);   // gemm A index
            ldsm4(ah, smem_u32(cPh + roff));
            ldsm4(al, smem_u32(cPl + roff));
            #pragma unroll
            for (int p = 0; p < 2; ++p) {
                uint32_t bh[4], bl[4];
                int boff = (ks + (lane & 15))*136 + wn + p*16 + ((lane >> 4) << 3);  // gemm B index
                ldsm4t(bh, smem_u32(cVh + boff));
                ldsm4t(bl, smem_u32(cVl + boff));
                #pragma unroll
                for (int nf = 0; nf < 2; ++nf) {
                    float* a = acc[p*2 + nf];
                    mma16816(a, ah, bh[2*nf], bh[2*nf+1]);
                    mma16816(a, ah, bl[2*nf], bl[2*nf+1]);
                    mma16816(a, al, bh[2*nf], bh[2*nf+1]);
                }
            }
        }
        if (c + 1 < 16) store_v_smem((c+1) & 1);
        __syncthreads();
    }

    // epilogue: normalize, transpose via smem (reuse P region as [128][40]), coalesced write
    __nv_bfloat16* Ath = sPh;
    __nv_bfloat16* Atl = sPl;
    int r0 = wm + (lane >> 2);
    float l0v = linv[r0], l1v = linv[r0 + 8];
    #pragma unroll
    for (int p = 0; p < 2; ++p)
        #pragma unroll
        for (int nf = 0; nf < 2; ++nf) {
            const float* a = acc[p*2 + nf];
            int nb = wn + p*16 + nf*8 + (lane & 3)*2;
            __nv_bfloat16 h, l;
            split_bf16(a[0]*l0v, h, l); Ath[(nb  )*40 + r0  ] = h; Atl[(nb  )*40 + r0  ] = l;
            split_bf16(a[1]*l0v, h, l); Ath[(nb+1)*40 + r0  ] = h; Atl[(nb+1)*40 + r0  ] = l;
            split_bf16(a[2]*l1v, h, l); Ath[(nb  )*40 + r0+8] = h; Atl[(nb  )*40 + r0+8] = l;
            split_bf16(a[3]*l1v, h, l); Ath[(nb+1)*40 + r0+8] = h; Atl[(nb+1)*40 + r0+8] = l;
        }
    __syncthreads();

    #pragma unroll
    for (int rep = 0; rep < 4; ++rep) {
        int u   = tid + rep*256;       // 0..1023
        int sel = u >> 9;              // 0 = hi, 1 = lo
        int v   = u & 511;
        int d   = v >> 2;
        int w8  = (v & 3) * 8;
        const __nv_bfloat16* src = (sel ? Atl : Ath) + d*40 + w8;
        __nv_bfloat16* dst = (sel ? g_al : g_ah) + slab + (size_t)d*NW + qw0 + w8;
        *(uint4*)dst = *(const uint4*)src;
    }
}

// ---------------- launch ----------------
extern "C" void kernel_launch(void* const* d_in, const int* in_sizes, int n_in,
                              void* d_out, int out_size)
{
    const float* x       = (const float*)d_in[0];
    const float* prevqk  = (const float*)d_in[1];
    const float* wq_conv = (const float*)d_in[2];
    const float* bq_conv = (const float*)d_in[3];
    const float* wq_lin  = (const float*)d_in[4];
    const float* wk_conv = (const float*)d_in[5];
    const float* bk_conv = (const float*)d_in[6];
    const float* wk_lin  = (const float*)d_in[7];
    const float* wv_conv = (const float*)d_in[8];
    const float* bv_conv = (const float*)d_in[9];
    const float* wv_lin  = (const float*)d_in[10];
    const float* wo_lin  = (const float*)d_in[11];
    float* out   = (float*)d_out;
    float* qkout = out + TENS;     // tuple output: (out, qk) concatenated

    int smGemm = (6*SA_ + 6*SB_) * 2;              // 113664 bytes (3 stages)
    int smQk   = (8*SB_) * 2;                      // 69632 bytes
    int smPv   = (2*16*PCH + 4*VBUF) * 2;          // 116736 bytes
    cudaFuncSetAttribute(gemm_mma, cudaFuncAttributeMaxDynamicSharedMemorySize, smGemm);
    cudaFuncSetAttribute(qk_mma,   cudaFuncAttributeMaxDynamicSharedMemorySize, smQk);
    cudaFuncSetAttribute(softmax_pv_mma, cudaFuncAttributeMaxDynamicSharedMemorySize, smPv);

    // 1) three convs fused -> bf16 hi/lo
    conv3_kernel<<<dim3(NW/32, NF/32, NB), 256>>>(
        x, wq_conv, bq_conv, wk_conv, bk_conv, wv_conv, bv_conv);

    // 2) weight conversion
    wconvert_kernel<<<(unsigned)((WSZ + 255)/256), 256>>>(wq_lin, wk_lin, wv_lin, wo_lin);

    // 3) mc_linear for q,k,v on tensor cores
    dim3 gg(NW/128, NF/128, NBC);
    gemm_mma<<<gg, 256, smGemm>>>(0, 0, nullptr);
    gemm_mma<<<gg, 256, smGemm>>>(1, 1, nullptr);
    gemm_mma<<<gg, 256, smGemm>>>(2, 2, nullptr);

    // 4) rotary on q,k -> bf16 hi/lo
    rotary_kernel<<<(unsigned)((TENS/2 + 255) / 256), 256>>>();

    // 5) QK^T logits -> qk output region
    qk_mma<<<dim3(NW/128, NW/128, NBC*NHEAD), 256, smQk>>>(prevqk, qkout);

    // 6) softmax @ V on tensor cores -> a (bf16 hi/lo)
    softmax_pv_mma<<<dim3(NW/32, NBC*NHEAD), 256, smPv>>>(qkout);

    // 7) output projection on tensor cores -> out region
    gemm_mma<<<gg, 256, smGemm>>>(3, 3, out);
}

// round 10
// speedup vs baseline: 1.2909x; 1.2909x over previous
#include <cuda_runtime.h>
#include <cuda_bf16.h>
#include <math.h>
#include <stdint.h>

#define NB 2
#define NC 8
#define NF 1024
#define NW 512
#define NHEAD 8
#define NHD 128
#define NBC (NB*NC)
#define TENS ((size_t)NB*NC*NF*NW)          // 8388608
#define WSZ  ((size_t)NC*NF*NF)             // 8388608 per weight tensor

// ---------------- scratch (static device globals; no runtime alloc) ----------------
__device__ __align__(16) __nv_bfloat16 g_cqh[TENS], g_cql[TENS];
__device__ __align__(16) __nv_bfloat16 g_ckh[TENS], g_ckl[TENS];
__device__ __align__(16) __nv_bfloat16 g_cvh[TENS], g_cvl[TENS];
__device__ __align__(16) __nv_bfloat16 g_qh[TENS], g_ql[TENS];
__device__ __align__(16) __nv_bfloat16 g_kh[TENS], g_kl[TENS];
__device__ __align__(16) __nv_bfloat16 g_vth[TENS], g_vtl[TENS];   // V transposed: [bc*8+h][w][d]
__device__ __align__(16) __nv_bfloat16 g_ah[TENS], g_al[TENS];
__device__ __align__(16) __nv_bfloat16 g_wh[4*WSZ], g_wl[4*WSZ];
__device__ __align__(16) float g_q[TENS], g_k[TENS];

// ---------------- helpers ----------------
__device__ __forceinline__ void split_bf16(float x, __nv_bfloat16& h, __nv_bfloat16& l) {
    h = __float2bfloat16(x);
    l = __float2bfloat16(x - __bfloat162float(h));
}
__device__ __forceinline__ uint32_t smem_u32(const void* p) {
    return (uint32_t)__cvta_generic_to_shared(p);
}
__device__ __forceinline__ void cp16(uint32_t dst, const void* src) {
    asm volatile("cp.async.cg.shared.global [%0], [%1], 16;" :: "r"(dst), "l"(src));
}
__device__ __forceinline__ void cp_commit() { asm volatile("cp.async.commit_group;"); }
template<int N> __device__ __forceinline__ void cp_wait() {
    asm volatile("cp.async.wait_group %0;" :: "n"(N));
}
__device__ __forceinline__ void ldsm4(uint32_t r[4], uint32_t addr) {
    asm volatile("ldmatrix.sync.aligned.m8n8.x4.shared.b16 {%0,%1,%2,%3},[%4];"
                 : "=r"(r[0]), "=r"(r[1]), "=r"(r[2]), "=r"(r[3]) : "r"(addr));
}
__device__ __forceinline__ void ldsm4t(uint32_t r[4], uint32_t addr) {
    asm volatile("ldmatrix.sync.aligned.m8n8.x4.trans.shared.b16 {%0,%1,%2,%3},[%4];"
                 : "=r"(r[0]), "=r"(r[1]), "=r"(r[2]), "=r"(r[3]) : "r"(addr));
}
__device__ __forceinline__ void mma16816(float c[4], const uint32_t a[4], uint32_t b0, uint32_t b1) {
    asm volatile("mma.sync.aligned.m16n8k16.row.col.f32.bf16.bf16.f32 "
                 "{%0,%1,%2,%3},{%4,%5,%6,%7},{%8,%9},{%0,%1,%2,%3};"
                 : "+f"(c[0]), "+f"(c[1]), "+f"(c[2]), "+f"(c[3])
                 : "r"(a[0]), "r"(a[1]), "r"(a[2]), "r"(a[3]), "r"(b0), "r"(b1));
}

// ---------------- fused 3x conv2d (3x3, pad 1, C=8 in/out) -> bf16 hi/lo ----------------
__global__ void __launch_bounds__(256) conv3_kernel(
    const float* __restrict__ x,
    const float* __restrict__ wq, const float* __restrict__ bq,
    const float* __restrict__ wk, const float* __restrict__ bk,
    const float* __restrict__ wv, const float* __restrict__ bv)
{
    __shared__ float xs[NC][34][36];
    __shared__ float ws[3*NC*NC*9];
    int tid = threadIdx.x;
    int bxo = blockIdx.x * 32;
    int byo = blockIdx.y * 32;
    int b   = blockIdx.z;

    for (int i = tid; i < NC*NC*9; i += 256) {
        ws[i]             = wq[i];
        ws[NC*NC*9 + i]   = wk[i];
        ws[2*NC*NC*9 + i] = wv[i];
    }
    for (int i = tid; i < NC*34*34; i += 256) {
        int ci = i / (34*34);
        int r  = (i / 34) % 34;
        int cl = i % 34;
        int gy = byo + r - 1, gx = bxo + cl - 1;
        float v = 0.f;
        if (gy >= 0 && gy < NF && gx >= 0 && gx < NW)
            v = x[(((size_t)b*NC + ci)*NF + gy)*NW + gx];
        xs[ci][r][cl] = v;
    }
    __syncthreads();

    #pragma unroll
    for (int p = 0; p < 4; ++p) {
        int pid = tid + p*256;
        int py = pid >> 5, px = pid & 31;
        float aq[NC], ak[NC], av[NC];
        #pragma unroll
        for (int co = 0; co < NC; ++co) { aq[co]=bq[co]; ak[co]=bk[co]; av[co]=bv[co]; }
        #pragma unroll
        for (int ci = 0; ci < NC; ++ci) {
            float w9[9];
            #pragma unroll
            for (int dy = 0; dy < 3; ++dy)
                #pragma unroll
                for (int dx = 0; dx < 3; ++dx)
                    w9[dy*3+dx] = xs[ci][py+dy][px+dx];
            #pragma unroll
            for (int co = 0; co < NC; ++co) {
                int wb = (co*NC + ci)*9;
                float sq=0.f, sk=0.f, sv=0.f;
                #pragma unroll
                for (int t = 0; t < 9; ++t) {
                    sq += w9[t]*ws[wb+t];
                    sk += w9[t]*ws[NC*NC*9 + wb+t];
                    sv += w9[t]*ws[2*NC*NC*9 + wb+t];
                }
                aq[co]+=sq; ak[co]+=sk; av[co]+=sv;
            }
        }
        int gy = byo + py, gx = bxo + px;
        #pragma unroll
        for (int co = 0; co < NC; ++co) {
            size_t o = (((size_t)b*NC+co)*NF + gy)*NW + gx;
            __nv_bfloat16 h, l;
            split_bf16(aq[co], h, l); g_cqh[o]=h; g_cql[o]=l;
            split_bf16(ak[co], h, l); g_ckh[o]=h; g_ckl[o]=l;
            split_bf16(av[co], h, l); g_cvh[o]=h; g_cvl[o]=l;
        }
    }
}

// ---------------- weight conversion: 4x (8,1024,1024) fp32 -> bf16 hi/lo ----------------
__global__ void __launch_bounds__(256) wconvert_kernel(
    const float* __restrict__ w0, const float* __restrict__ w1,
    const float* __restrict__ w2, const float* __restrict__ w3)
{
    size_t i = (size_t)blockIdx.x * blockDim.x + threadIdx.x;
    if (i >= WSZ) return;
    __nv_bfloat16 h, l;
    split_bf16(w0[i], h, l); g_wh[i]         = h; g_wl[i]         = l;
    split_bf16(w1[i], h, l); g_wh[WSZ + i]   = h; g_wl[WSZ + i]   = l;
    split_bf16(w2[i], h, l); g_wh[2*WSZ + i] = h; g_wl[2*WSZ + i] = l;
    split_bf16(w3[i], h, l); g_wh[3*WSZ + i] = h; g_wl[3*WSZ + i] = l;
}

// ---------------- mc_linear batched GEMM via bf16 tensor cores (3x split) ----------------
// C[z][m][n] = sum_k W[z%8][m][k] * B[z][k][n]; M=1024 N=512 K=1024
// CTA 128x128, BK=32, 3-stage cp.async pipeline, 8 warps, warp tile 32x64.
// bsel==2 (V): transposed bf16 hi/lo epilogue into [head][w][d] via smem.
#define SA_ (128*40)
#define SB_ (32*136)
__global__ void __launch_bounds__(256, 2) gemm_mma(int wsel, int bsel, float* __restrict__ Cext)
{
    extern __shared__ __nv_bfloat16 sm_[];
    __nv_bfloat16* sAh = sm_;
    __nv_bfloat16* sAl = sAh + 3*SA_;
    __nv_bfloat16* sBh = sAl + 3*SA_;
    __nv_bfloat16* sBl = sBh + 3*SB_;

    int z = blockIdx.z;
    const __nv_bfloat16* Ah = g_wh + (size_t)wsel*WSZ + (size_t)(z & 7)*NF*NF;
    const __nv_bfloat16* Al = g_wl + (size_t)wsel*WSZ + (size_t)(z & 7)*NF*NF;
    const __nv_bfloat16 *BhG, *BlG;
    switch (bsel) {
        case 0:  BhG = g_cqh; BlG = g_cql; break;
        case 1:  BhG = g_ckh; BlG = g_ckl; break;
        case 2:  BhG = g_cvh; BlG = g_cvl; break;
        default: BhG = g_ah;  BlG = g_al;  break;
    }
    const __nv_bfloat16* Bh = BhG + (size_t)z*NF*NW;
    const __nv_bfloat16* Bl = BlG + (size_t)z*NF*NW;

    int m0 = blockIdx.y*128, n0 = blockIdx.x*128;
    int tid = threadIdx.x;
    int lane = tid & 31, wrp = tid >> 5;
    int wm = (wrp >> 1)*32, wn = (wrp & 1)*64;

    int arow = tid >> 1, acol = (tid & 1)*16;
    int brow = tid >> 3, bcol = (tid & 7)*8;

    float acc[2][8][4];
    #pragma unroll
    for (int i = 0; i < 2; ++i)
        #pragma unroll
        for (int j = 0; j < 8; ++j)
            #pragma unroll
            for (int t = 0; t < 4; ++t) acc[i][j][t] = 0.f;

    auto load_stage = [&](int s, int k0) {
        {
            const __nv_bfloat16* gh = Ah + (size_t)(m0 + arow)*NF + k0 + acol;
            const __nv_bfloat16* gl = Al + (size_t)(m0 + arow)*NF + k0 + acol;
            uint32_t dh = smem_u32(sAh + s*SA_ + arow*40 + acol);
            uint32_t dl = smem_u32(sAl + s*SA_ + arow*40 + acol);
            cp16(dh, gh); cp16(dh+16, gh+8);
            cp16(dl, gl); cp16(dl+16, gl+8);
        }
        {
            const __nv_bfloat16* gh = Bh + (size_t)(k0 + brow)*NW + n0 + bcol;
            const __nv_bfloat16* gl = Bl + (size_t)(k0 + brow)*NW + n0 + bcol;
            uint32_t dh = smem_u32(sBh + s*SB_ + brow*136 + bcol);
            uint32_t dl = smem_u32(sBl + s*SB_ + brow*136 + bcol);
            cp16(dh, gh); cp16(dh+128, gh+64);
            cp16(dl, gl); cp16(dl+128, gl+64);
        }
    };

    load_stage(0, 0);  cp_commit();
    load_stage(1, 32); cp_commit();
    const int KT = NF/32;
    for (int kt = 0; kt < KT; ++kt) {
        if (kt + 1 < KT) cp_wait<1>(); else cp_wait<0>();
        __syncthreads();
        if (kt + 2 < KT) { load_stage((kt+2)%3, (kt+2)*32); cp_commit(); }
        int s = kt % 3;
        const __nv_bfloat16* cAh = sAh + s*SA_;
        const __nv_bfloat16* cAl = sAl + s*SA_;
        const __nv_bfloat16* cBh = sBh + s*SB_;
        const __nv_bfloat16* cBl = sBl + s*SB_;
        #pragma unroll
        for (int ks = 0; ks < 32; ks += 16) {
            uint32_t ahf[2][4], alf[2][4];
            #pragma unroll
            for (int mt = 0; mt < 2; ++mt) {
                int roff = (wm + mt*16 + (lane & 15))*40 + ks + ((lane >> 4) << 3);
                ldsm4(ahf[mt], smem_u32(cAh + roff));
                ldsm4(alf[mt], smem_u32(cAl + roff));
            }
            #pragma unroll
            for (int p = 0; p < 4; ++p) {
                uint32_t bhf[4], blf[4];
                int boff = (ks + (lane & 15))*136 + wn + p*16 + ((lane >> 4) << 3);
                ldsm4t(bhf, smem_u32(cBh + boff));
                ldsm4t(blf, smem_u32(cBl + boff));
                #pragma unroll
                for (int mt = 0; mt < 2; ++mt) {
                    mma16816(acc[mt][2*p],   ahf[mt], bhf[0], bhf[1]);
                    mma16816(acc[mt][2*p],   ahf[mt], blf[0], blf[1]);
                    mma16816(acc[mt][2*p],   alf[mt], bhf[0], bhf[1]);
                    mma16816(acc[mt][2*p+1], ahf[mt], bhf[2], bhf[3]);
                    mma16816(acc[mt][2*p+1], ahf[mt], blf[2], blf[3]);
                    mma16816(acc[mt][2*p+1], alf[mt], bhf[2], bhf[3]);
                }
            }
        }
    }

    if (bsel == 2) {
        // V: transpose through smem, write bf16 hi/lo to [head][w][d] (d contiguous)
        float* T = (float*)sm_;   // [128 w][pitch 132]
        __syncthreads();
        #pragma unroll
        for (int mt = 0; mt < 2; ++mt)
            #pragma unroll
            for (int nt = 0; nt < 8; ++nt) {
                int r = wm + mt*16 + (lane >> 2);       // d within head
                int c = wn + nt*8 + (lane & 3)*2;       // w within tile
                T[(c  )*132 + r    ] = acc[mt][nt][0];
                T[(c+1)*132 + r    ] = acc[mt][nt][1];
                T[(c  )*132 + r + 8] = acc[mt][nt][2];
                T[(c+1)*132 + r + 8] = acc[mt][nt][3];
            }
        __syncthreads();
        // block covers exactly one head: h = blockIdx.y (m0 = h*128), d = r
        size_t vbase = (((size_t)z*NHEAD + blockIdx.y)*NW + n0) * NHD;
        #pragma unroll
        for (int i = 0; i < 8; ++i) {
            int u = tid + i*256;            // 0..2047
            int w = u >> 4, seg = (u & 15)*8;
            const float* src = T + w*132 + seg;
            __align__(16) __nv_bfloat16 hh[8], ll[8];
            #pragma unroll
            for (int j = 0; j < 8; ++j) split_bf16(src[j], hh[j], ll[j]);
            size_t o = vbase + (size_t)w*NHD + seg;
            *(uint4*)&g_vth[o] = *(const uint4*)hh;
            *(uint4*)&g_vtl[o] = *(const uint4*)ll;
        }
    } else {
        float* C = (bsel == 0 ? g_q : bsel == 1 ? g_k : Cext) + (size_t)z*NF*NW;
        #pragma unroll
        for (int mt = 0; mt < 2; ++mt)
            #pragma unroll
            for (int nt = 0; nt < 8; ++nt) {
                int r = m0 + wm + mt*16 + (lane >> 2);
                int c = n0 + wn + nt*8 + (lane & 3)*2;
                *(float2*)&C[(size_t)r*NW + c]     = make_float2(acc[mt][nt][0], acc[mt][nt][1]);
                *(float2*)&C[(size_t)(r+8)*NW + c] = make_float2(acc[mt][nt][2], acc[mt][nt][3]);
            }
    }
}

// ---------------- rotary on g_q/g_k (fp32 in) -> bf16 hi/lo out ----------------
__global__ void __launch_bounds__(256) rotary_kernel()
{
    size_t idx = (size_t)blockIdx.x * blockDim.x + threadIdx.x;
    if (idx >= TENS/2) return;
    int w    = (int)(idx % NW);
    size_t t = idx / NW;
    int fp = (int)(t % (NF/2));
    int bc = (int)(t / (NF/2));
    int f  = fp * 2;
    int d  = f & (NHD - 1);
    float inv = exp2f((float)d * (-13.287712379549449f / 128.0f));
    float th  = (float)w * inv;
    float sn, cs;
    sincosf(th, &sn, &cs);
    size_t i0 = ((size_t)bc*NF + f)*NW + w;
    size_t i1 = i0 + NW;
    __nv_bfloat16 h, l;
    float x1 = g_q[i0], x2 = g_q[i1];
    float r0 = x1*cs - x2*sn, r1 = x2*cs + x1*sn;
    split_bf16(r0, h, l); g_qh[i0]=h; g_ql[i0]=l;
    split_bf16(r1, h, l); g_qh[i1]=h; g_ql[i1]=l;
    x1 = g_k[i0]; x2 = g_k[i1];
    r0 = x1*cs - x2*sn; r1 = x2*cs + x1*sn;
    split_bf16(r0, h, l); g_kh[i0]=h; g_kl[i0]=l;
    split_bf16(r1, h, l); g_kh[i1]=h; g_kl[i1]=l;
}

// ---------------- QK^T logits via tensor cores: S = Q^T K / 32 + prev ----------------
__global__ void __launch_bounds__(256, 2) qk_mma(
    const float* __restrict__ prev, float* __restrict__ qkout)
{
    extern __shared__ __nv_bfloat16 sm_[];
    __nv_bfloat16* sAh = sm_;
    __nv_bfloat16* sAl = sAh + 2*SB_;
    __nv_bfloat16* sBh = sAl + 2*SB_;
    __nv_bfloat16* sBl = sBh + 2*SB_;

    int hz = blockIdx.z;
    int bc = hz >> 3, hd = hz & 7;
    size_t slab = ((size_t)bc*NF + hd*NHD)*NW;
    const __nv_bfloat16* QhG = g_qh + slab;
    const __nv_bfloat16* QlG = g_ql + slab;
    const __nv_bfloat16* KhG = g_kh + slab;
    const __nv_bfloat16* KlG = g_kl + slab;

    int m0 = blockIdx.y*128, n0 = blockIdx.x*128;
    int tid = threadIdx.x;
    int lane = tid & 31, wrp = tid >> 5;
    int wm = (wrp >> 1)*32, wn = (wrp & 1)*64;

    int lrow = tid >> 3, lcol = (tid & 7)*8;

    float acc[2][8][4];
    #pragma unroll
    for (int i = 0; i < 2; ++i)
        #pragma unroll
        for (int j = 0; j < 8; ++j)
            #pragma unroll
            for (int t = 0; t < 4; ++t) acc[i][j][t] = 0.f;

    auto load_stage = [&](int s, int k0) {
        size_t grow = (size_t)(k0 + lrow)*NW;
        {
            const __nv_bfloat16* gh = QhG + grow + m0 + lcol;
            const __nv_bfloat16* gl = QlG + grow + m0 + lcol;
            uint32_t dh = smem_u32(sAh + s*SB_ + lrow*136 + lcol);
            uint32_t dl = smem_u32(sAl + s*SB_ + lrow*136 + lcol);
            cp16(dh, gh); cp16(dh+128, gh+64);
            cp16(dl, gl); cp16(dl+128, gl+64);
        }
        {
            const __nv_bfloat16* gh = KhG + grow + n0 + lcol;
            const __nv_bfloat16* gl = KlG + grow + n0 + lcol;
            uint32_t dh = smem_u32(sBh + s*SB_ + lrow*136 + lcol);
            uint32_t dl = smem_u32(sBl + s*SB_ + lrow*136 + lcol);
            cp16(dh, gh); cp16(dh+128, gh+64);
            cp16(dl, gl); cp16(dl+128, gl+64);
        }
    };

    load_stage(0, 0);
    cp_commit();
    const int KT = NHD/32;   // 4
    for (int kt = 0; kt < KT; ++kt) {
        if (kt + 1 < KT) { load_stage((kt+1)&1, (kt+1)*32); cp_commit(); cp_wait<1>(); }
        else             { cp_wait<0>(); }
        __syncthreads();
        int s = kt & 1;
        const __nv_bfloat16* cAh = sAh + s*SB_;
        const __nv_bfloat16* cAl = sAl + s*SB_;
        const __nv_bfloat16* cBh = sBh + s*SB_;
        const __nv_bfloat16* cBl = sBl + s*SB_;
        #pragma unroll
        for (int ks = 0; ks < 32; ks += 16) {
            uint32_t ahf[2][4], alf[2][4];
            #pragma unroll
            for (int mt = 0; mt < 2; ++mt) {
                int off = (ks + (lane & 7) + ((lane >> 4) << 3))*136
                        + wm + mt*16 + (((lane >> 3) & 1) << 3);
                ldsm4t(ahf[mt], smem_u32(cAh + off));
                ldsm4t(alf[mt], smem_u32(cAl + off));
            }
            #pragma unroll
            for (int p = 0; p < 4; ++p) {
                uint32_t bhf[4], blf[4];
                int boff = (ks + (lane & 15))*136 + wn + p*16 + ((lane >> 4) << 3);
                ldsm4t(bhf, smem_u32(cBh + boff));
                ldsm4t(blf, smem_u32(cBl + boff));
                #pragma unroll
                for (int mt = 0; mt < 2; ++mt) {
                    mma16816(acc[mt][2*p],   ahf[mt], bhf[0], bhf[1]);
                    mma16816(acc[mt][2*p],   ahf[mt], blf[0], blf[1]);
                    mma16816(acc[mt][2*p],   alf[mt], bhf[0], bhf[1]);
                    mma16816(acc[mt][2*p+1], ahf[mt], bhf[2], bhf[3]);
                    mma16816(acc[mt][2*p+1], ahf[mt], blf[2], blf[3]);
                    mma16816(acc[mt][2*p+1], alf[mt], bhf[2], bhf[3]);
                }
            }
        }
        __syncthreads();
    }

    const float scale = 1.0f / 32.0f;   // 1/sqrt(F)
    size_t base = (size_t)hz * NW * NW;
    #pragma unroll
    for (int mt = 0; mt < 2; ++mt)
        #pragma unroll
        for (int nt = 0; nt < 8; ++nt) {
            int r = m0 + wm + mt*16 + (lane >> 2);
            int c = n0 + wn + nt*8 + (lane & 3)*2;
            size_t o0 = base + (size_t)r*NW + c;
            size_t o1 = base + (size_t)(r+8)*NW + c;
            float2 p0 = *(const float2*)&prev[o0];
            float2 p1 = *(const float2*)&prev[o1];
            *(float2*)&qkout[o0] = make_float2(acc[mt][nt][0]*scale + p0.x,
                                               acc[mt][nt][1]*scale + p0.y);
            *(float2*)&qkout[o1] = make_float2(acc[mt][nt][2]*scale + p1.x,
                                               acc[mt][nt][3]*scale + p1.y);
        }
}

// ---------------- softmax(S) @ V on tensor cores (validated layouts, cp.async V feed) ------
// CTA = (32 q-rows, head). P chunked: 16 chunks x [32 rows][pitch 40] (R7-validated).
// V pre-split+transposed in gmem [head][w][d] -> cp.async rows into [kw][136] (R7-validated).
#define PCH (32*40)       // one P chunk: 1280 elements
#define VBUF (32*136)     // one V buffer: 4352 elements
__global__ void __launch_bounds__(256) softmax_pv_mma(const float* __restrict__ qk)
{
    extern __shared__ __nv_bfloat16 pv_[];
    __nv_bfloat16* sPh = pv_;                 // 16*PCH
    __nv_bfloat16* sPl = sPh + 16*PCH;        // 16*PCH
    __nv_bfloat16* sV  = sPl + 16*PCH;        // 2 stages x (hi|lo) x VBUF
    __shared__ float linv[32];

    int hz  = blockIdx.y;
    int qt  = blockIdx.x;
    int bc  = hz >> 3, hd = hz & 7;
    int qw0 = qt * 32;
    size_t slab = ((size_t)bc*NF + hd*NHD)*NW;          // for output a
    size_t vtb  = (size_t)hz * NW * NHD;                // transposed V base
    const float* S = qk + ((size_t)hz * NW + qw0) * NW;

    int tid = threadIdx.x;
    int lane = tid & 31, wrp = tid >> 5;

    auto load_v = [&](int stage, int kw0) {
        __nv_bfloat16* bh = sV + stage*2*VBUF;
        #pragma unroll
        for (int rep = 0; rep < 2; ++rep) {
            int u  = tid + rep*256;         // 0..511
            int kw = u >> 4, seg = (u & 15)*8;
            size_t src = vtb + (size_t)(kw0 + kw)*NHD + seg;
            cp16(smem_u32(bh + kw*136 + seg),        g_vth + src);
            cp16(smem_u32(bh + VBUF + kw*136 + seg), g_vtl + src);
        }
    };
    load_v(0, 0);  cp_commit();
    load_v(1, 32); cp_commit();

    // softmax: warp w handles rows w*4 .. w*4+3; one global read, exp in regs
    #pragma unroll
    for (int j = 0; j < 4; ++j) {
        int row = wrp*4 + j;
        const float* Sr = S + (size_t)row*NW;
        float v[16];
        #pragma unroll
        for (int i = 0; i < 4; ++i)
            *(float4*)&v[i*4] = *(const float4*)&Sr[i*128 + lane*4];
        float m = v[0];
        #pragma unroll
        for (int i = 1; i < 16; ++i) m = fmaxf(m, v[i]);
        #pragma unroll
        for (int o = 16; o; o >>= 1) m = fmaxf(m, __shfl_xor_sync(0xffffffffu, m, o));
        float s = 0.f;
        #pragma unroll
        for (int i = 0; i < 16; ++i) { v[i] = __expf(v[i] - m); s += v[i]; }
        #pragma unroll
        for (int o = 16; o; o >>= 1) s += __shfl_xor_sync(0xffffffffu, s, o);
        if (lane == 0) linv[row] = 1.f / s;
        #pragma unroll
        for (int i = 0; i < 4; ++i) {
            int ch = i*4 + (lane >> 3);
            int kb = (lane & 7)*4;
            int base = ch*PCH + row*40 + kb;
            __nv_bfloat16 h0,l0,h1,l1,h2,l2,h3,l3;
            split_bf16(v[i*4+0], h0, l0); split_bf16(v[i*4+1], h1, l1);
            split_bf16(v[i*4+2], h2, l2); split_bf16(v[i*4+3], h3, l3);
            *(__nv_bfloat162*)&sPh[base]     = __nv_bfloat162(h0, h1);
            *(__nv_bfloat162*)&sPh[base + 2] = __nv_bfloat162(h2, h3);
            *(__nv_bfloat162*)&sPl[base]     = __nv_bfloat162(l0, l1);
            *(__nv_bfloat162*)&sPl[base + 2] = __nv_bfloat162(l2, l3);
        }
    }
    __syncthreads();

    // MMA: 8 warps, warp tile m16 x n32: wm in {0,16}, wn in {0,32,64,96}
    int wm = (wrp >> 2)*16;
    int wn = (wrp & 3)*32;
    float acc[4][4];
    #pragma unroll
    for (int f = 0; f < 4; ++f)
        #pragma unroll
        for (int t = 0; t < 4; ++t) acc[f][t] = 0.f;

    for (int c = 0; c < 16; ++c) {
        if (c == 15) cp_wait<0>(); else cp_wait<1>();
        __syncthreads();
        const __nv_bfloat16* cVh = sV + (c & 1)*2*VBUF;
        const __nv_bfloat16* cVl = cVh + VBUF;
        const __nv_bfloat16* cPh = sPh + c*PCH;
        const __nv_bfloat16* cPl = sPl + c*PCH;
        #pragma unroll
        for (int ks = 0; ks < 32; ks += 16) {
            uint32_t ah[4], al[4];
            int roff = (wm + (lane & 15))*40 + ks + ((lane >> 4) << 3);   // gemm A index
            ldsm4(ah, smem_u32(cPh + roff));
            ldsm4(al, smem_u32(cPl + roff));
            #pragma unroll
            for (int p = 0; p < 2; ++p) {
                uint32_t bh[4], bl[4];
                int boff = (ks + (lane & 15))*136 + wn + p*16 + ((lane >> 4) << 3);  // gemm B index
                ldsm4t(bh, smem_u32(cVh + boff));
                ldsm4t(bl, smem_u32(cVl + boff));
                #pragma unroll
                for (int nf = 0; nf < 2; ++nf) {
                    float* a = acc[p*2 + nf];
                    mma16816(a, ah, bh[2*nf], bh[2*nf+1]);
                    mma16816(a, ah, bl[2*nf], bl[2*nf+1]);
                    mma16816(a, al, bh[2*nf], bh[2*nf+1]);
                }
            }
        }
        __syncthreads();
        if (c + 2 < 16) { load_v(c & 1, (c+2)*32); cp_commit(); }
    }

    // epilogue: normalize, transpose via smem (reuse P region as [128][40]), coalesced write
    __nv_bfloat16* Ath = sPh;
    __nv_bfloat16* Atl = sPl;
    int r0 = wm + (lane >> 2);
    float l0v = linv[r0], l1v = linv[r0 + 8];
    #pragma unroll
    for (int p = 0; p < 2; ++p)
        #pragma unroll
        for (int nf = 0; nf < 2; ++nf) {
            const float* a = acc[p*2 + nf];
            int nb = wn + p*16 + nf*8 + (lane & 3)*2;
            __nv_bfloat16 h, l;
            split_bf16(a[0]*l0v, h, l); Ath[(nb  )*40 + r0  ] = h; Atl[(nb  )*40 + r0  ] = l;
            split_bf16(a[1]*l0v, h, l); Ath[(nb+1)*40 + r0  ] = h; Atl[(nb+1)*40 + r0  ] = l;
            split_bf16(a[2]*l1v, h, l); Ath[(nb  )*40 + r0+8] = h; Atl[(nb  )*40 + r0+8] = l;
            split_bf16(a[3]*l1v, h, l); Ath[(nb+1)*40 + r0+8] = h; Atl[(nb+1)*40 + r0+8] = l;
        }
    __syncthreads();

    #pragma unroll
    for (int rep = 0; rep < 4; ++rep) {
        int u   = tid + rep*256;       // 0..1023
        int sel = u >> 9;              // 0 = hi, 1 = lo
        int v   = u & 511;
        int d   = v >> 2;
        int w8  = (v & 3) * 8;
        const __nv_bfloat16* src = (sel ? Atl : Ath) + d*40 + w8;
        __nv_bfloat16* dst = (sel ? g_al : g_ah) + slab + (size_t)d*NW + qw0 + w8;
        *(uint4*)dst = *(const uint4*)src;
    }
}

// ---------------- launch ----------------
extern "C" void kernel_launch(void* const* d_in, const int* in_sizes, int n_in,
                              void* d_out, int out_size)
{
    const float* x       = (const float*)d_in[0];
    const float* prevqk  = (const float*)d_in[1];
    const float* wq_conv = (const float*)d_in[2];
    const float* bq_conv = (const float*)d_in[3];
    const float* wq_lin  = (const float*)d_in[4];
    const float* wk_conv = (const float*)d_in[5];
    const float* bk_conv = (const float*)d_in[6];
    const float* wk_lin  = (const float*)d_in[7];
    const float* wv_conv = (const float*)d_in[8];
    const float* bv_conv = (const float*)d_in[9];
    const float* wv_lin  = (const float*)d_in[10];
    const float* wo_lin  = (const float*)d_in[11];
    float* out   = (float*)d_out;
    float* qkout = out + TENS;     // tuple output: (out, qk) concatenated

    int smGemm = (6*SA_ + 6*SB_) * 2;              // 113664 bytes (3 stages)
    int smQk   = (8*SB_) * 2;                      // 69632 bytes
    int smPv   = (2*16*PCH + 4*VBUF) * 2;          // 116736 bytes
    cudaFuncSetAttribute(gemm_mma, cudaFuncAttributeMaxDynamicSharedMemorySize, smGemm);
    cudaFuncSetAttribute(qk_mma,   cudaFuncAttributeMaxDynamicSharedMemorySize, smQk);
    cudaFuncSetAttribute(softmax_pv_mma, cudaFuncAttributeMaxDynamicSharedMemorySize, smPv);

    // 1) three convs fused -> bf16 hi/lo
    conv3_kernel<<<dim3(NW/32, NF/32, NB), 256>>>(
        x, wq_conv, bq_conv, wk_conv, bk_conv, wv_conv, bv_conv);

    // 2) weight conversion
    wconvert_kernel<<<(unsigned)((WSZ + 255)/256), 256>>>(wq_lin, wk_lin, wv_lin, wo_lin);

    // 3) mc_linear for q,k,v on tensor cores (v -> bf16 hi/lo transposed)
    dim3 gg(NW/128, NF/128, NBC);
    gemm_mma<<<gg, 256, smGemm>>>(0, 0, nullptr);
    gemm_mma<<<gg, 256, smGemm>>>(1, 1, nullptr);
    gemm_mma<<<gg, 256, smGemm>>>(2, 2, nullptr);

    // 4) rotary on q,k -> bf16 hi/lo
    rotary_kernel<<<(unsigned)((TENS/2 + 255) / 256), 256>>>();

    // 5) QK^T logits -> qk output region
    qk_mma<<<dim3(NW/128, NW/128, NBC*NHEAD), 256, smQk>>>(prevqk, qkout);

    // 6) softmax @ V on tensor cores -> a (bf16 hi/lo)
    softmax_pv_mma<<<dim3(NW/32, NBC*NHEAD), 256, smPv>>>(qkout);

    // 7) output projection on tensor cores -> out region
    gemm_mma<<<gg, 256, smGemm>>>(3, 3, out);
}

// round 15
// speedup vs baseline: 1.3096x; 1.0145x over previous
#include <cuda_runtime.h>
#include <cuda_bf16.h>
#include <math.h>
#include <stdint.h>

#define NB 2
#define NC 8
#define NF 1024
#define NW 512
#define NHEAD 8
#define NHD 128
#define NBC (NB*NC)
#define TENS ((size_t)NB*NC*NF*NW)          // 8388608
#define WSZ  ((size_t)NC*NF*NF)             // 8388608 per weight tensor

// ---------------- scratch (static device globals; no runtime alloc) ----------------
__device__ __align__(16) __nv_bfloat16 g_cqh[TENS], g_cql[TENS];
__device__ __align__(16) __nv_bfloat16 g_ckh[TENS], g_ckl[TENS];
__device__ __align__(16) __nv_bfloat16 g_cvh[TENS], g_cvl[TENS];
__device__ __align__(16) __nv_bfloat16 g_qh[TENS], g_ql[TENS];
__device__ __align__(16) __nv_bfloat16 g_kh[TENS], g_kl[TENS];
__device__ __align__(16) __nv_bfloat16 g_vth[TENS], g_vtl[TENS];   // V transposed: [bc*8+h][w][d]
__device__ __align__(16) __nv_bfloat16 g_ah[TENS], g_al[TENS];
__device__ __align__(16) __nv_bfloat16 g_wh[4*WSZ], g_wl[4*WSZ];

// ---------------- helpers ----------------
__device__ __forceinline__ void split_bf16(float x, __nv_bfloat16& h, __nv_bfloat16& l) {
    h = __float2bfloat16(x);
    l = __float2bfloat16(x - __bfloat162float(h));
}
__device__ __forceinline__ uint32_t smem_u32(const void* p) {
    return (uint32_t)__cvta_generic_to_shared(p);
}
__device__ __forceinline__ void cp16(uint32_t dst, const void* src) {
    asm volatile("cp.async.cg.shared.global [%0], [%1], 16;" :: "r"(dst), "l"(src));
}
__device__ __forceinline__ void cp_commit() { asm volatile("cp.async.commit_group;"); }
template<int N> __device__ __forceinline__ void cp_wait() {
    asm volatile("cp.async.wait_group %0;" :: "n"(N));
}
__device__ __forceinline__ void ldsm4(uint32_t r[4], uint32_t addr) {
    asm volatile("ldmatrix.sync.aligned.m8n8.x4.shared.b16 {%0,%1,%2,%3},[%4];"
                 : "=r"(r[0]), "=r"(r[1]), "=r"(r[2]), "=r"(r[3]) : "r"(addr));
}
__device__ __forceinline__ void ldsm4t(uint32_t r[4], uint32_t addr) {
    asm volatile("ldmatrix.sync.aligned.m8n8.x4.trans.shared.b16 {%0,%1,%2,%3},[%4];"
                 : "=r"(r[0]), "=r"(r[1]), "=r"(r[2]), "=r"(r[3]) : "r"(addr));
}
__device__ __forceinline__ void mma16816(float c[4], const uint32_t a[4], uint32_t b0, uint32_t b1) {
    asm volatile("mma.sync.aligned.m16n8k16.row.col.f32.bf16.bf16.f32 "
                 "{%0,%1,%2,%3},{%4,%5,%6,%7},{%8,%9},{%0,%1,%2,%3};"
                 : "+f"(c[0]), "+f"(c[1]), "+f"(c[2]), "+f"(c[3])
                 : "r"(a[0]), "r"(a[1]), "r"(a[2]), "r"(a[3]), "r"(b0), "r"(b1));
}

// ---------------- fused 3x conv2d (3x3, pad 1, C=8 in/out) -> bf16 hi/lo ----------------
__global__ void __launch_bounds__(256) conv3_kernel(
    const float* __restrict__ x,
    const float* __restrict__ wq, const float* __restrict__ bq,
    const float* __restrict__ wk, const float* __restrict__ bk,
    const float* __restrict__ wv, const float* __restrict__ bv)
{
    __shared__ float xs[NC][34][36];
    __shared__ float ws[3*NC*NC*9];
    int tid = threadIdx.x;
    int bxo = blockIdx.x * 32;
    int byo = blockIdx.y * 32;
    int b   = blockIdx.z;

    for (int i = tid; i < NC*NC*9; i += 256) {
        ws[i]             = wq[i];
        ws[NC*NC*9 + i]   = wk[i];
        ws[2*NC*NC*9 + i] = wv[i];
    }
    for (int i = tid; i < NC*34*34; i += 256) {
        int ci = i / (34*34);
        int r  = (i / 34) % 34;
        int cl = i % 34;
        int gy = byo + r - 1, gx = bxo + cl - 1;
        float v = 0.f;
        if (gy >= 0 && gy < NF && gx >= 0 && gx < NW)
            v = x[(((size_t)b*NC + ci)*NF + gy)*NW + gx];
        xs[ci][r][cl] = v;
    }
    __syncthreads();

    #pragma unroll
    for (int p = 0; p < 4; ++p) {
        int pid = tid + p*256;
        int py = pid >> 5, px = pid & 31;
        float aq[NC], ak[NC], av[NC];
        #pragma unroll
        for (int co = 0; co < NC; ++co) { aq[co]=bq[co]; ak[co]=bk[co]; av[co]=bv[co]; }
        #pragma unroll
        for (int ci = 0; ci < NC; ++ci) {
            float w9[9];
            #pragma unroll
            for (int dy = 0; dy < 3; ++dy)
                #pragma unroll
                for (int dx = 0; dx < 3; ++dx)
                    w9[dy*3+dx] = xs[ci][py+dy][px+dx];
            #pragma unroll
            for (int co = 0; co < NC; ++co) {
                int wb = (co*NC + ci)*9;
                float sq=0.f, sk=0.f, sv=0.f;
                #pragma unroll
                for (int t = 0; t < 9; ++t) {
                    sq += w9[t]*ws[wb+t];
                    sk += w9[t]*ws[NC*NC*9 + wb+t];
                    sv += w9[t]*ws[2*NC*NC*9 + wb+t];
                }
                aq[co]+=sq; ak[co]+=sk; av[co]+=sv;
            }
        }
        int gy = byo + py, gx = bxo + px;
        #pragma unroll
        for (int co = 0; co < NC; ++co) {
            size_t o = (((size_t)b*NC+co)*NF + gy)*NW + gx;
            __nv_bfloat16 h, l;
            split_bf16(aq[co], h, l); g_cqh[o]=h; g_cql[o]=l;
            split_bf16(ak[co], h, l); g_ckh[o]=h; g_ckl[o]=l;
            split_bf16(av[co], h, l); g_cvh[o]=h; g_cvl[o]=l;
        }
    }
}

// ---------------- weight conversion: 4x (8,1024,1024) fp32 -> bf16 hi/lo ----------------
__global__ void __launch_bounds__(256) wconvert_kernel(
    const float* __restrict__ w0, const float* __restrict__ w1,
    const float* __restrict__ w2, const float* __restrict__ w3)
{
    size_t i = (size_t)blockIdx.x * blockDim.x + threadIdx.x;
    if (i >= WSZ) return;
    __nv_bfloat16 h, l;
    split_bf16(w0[i], h, l); g_wh[i]         = h; g_wl[i]         = l;
    split_bf16(w1[i], h, l); g_wh[WSZ + i]   = h; g_wl[WSZ + i]   = l;
    split_bf16(w2[i], h, l); g_wh[2*WSZ + i] = h; g_wl[2*WSZ + i] = l;
    split_bf16(w3[i], h, l); g_wh[3*WSZ + i] = h; g_wl[3*WSZ + i] = l;
}

// ---------------- mc_linear batched GEMM via bf16 tensor cores (3x split) ----------------
// C[z][m][n] = sum_k W[z%8][m][k] * B[z][k][n]; M=1024 N=512 K=1024
// CTA 128x128, BK=32, 3-stage cp.async pipeline, 8 warps, warp tile 32x64.
// bsel 0/1 (q/k): rotary fused in epilogue (pair exchange via shfl_xor 4), bf16 hi/lo out.
// bsel 2   (V)  : transposed bf16 hi/lo epilogue into [head][w][d] via smem.
// bsel 3   (out): plain fp32 write to Cext.
#define SA_ (128*40)
#define SB_ (32*136)
__global__ void __launch_bounds__(256, 2) gemm_mma(int wsel, int bsel, float* __restrict__ Cext)
{
    extern __shared__ __nv_bfloat16 sm_[];
    __nv_bfloat16* sAh = sm_;
    __nv_bfloat16* sAl = sAh + 3*SA_;
    __nv_bfloat16* sBh = sAl + 3*SA_;
    __nv_bfloat16* sBl = sBh + 3*SB_;

    int z = blockIdx.z;
    const __nv_bfloat16* Ah = g_wh + (size_t)wsel*WSZ + (size_t)(z & 7)*NF*NF;
    const __nv_bfloat16* Al = g_wl + (size_t)wsel*WSZ + (size_t)(z & 7)*NF*NF;
    const __nv_bfloat16 *BhG, *BlG;
    switch (bsel) {
        case 0:  BhG = g_cqh; BlG = g_cql; break;
        case 1:  BhG = g_ckh; BlG = g_ckl; break;
        case 2:  BhG = g_cvh; BlG = g_cvl; break;
        default: BhG = g_ah;  BlG = g_al;  break;
    }
    const __nv_bfloat16* Bh = BhG + (size_t)z*NF*NW;
    const __nv_bfloat16* Bl = BlG + (size_t)z*NF*NW;

    int m0 = blockIdx.y*128, n0 = blockIdx.x*128;
    int tid = threadIdx.x;
    int lane = tid & 31, wrp = tid >> 5;
    int wm = (wrp >> 1)*32, wn = (wrp & 1)*64;

    int arow = tid >> 1, acol = (tid & 1)*16;
    int brow = tid >> 3, bcol = (tid & 7)*8;

    float acc[2][8][4];
    #pragma unroll
    for (int i = 0; i < 2; ++i)
        #pragma unroll
        for (int j = 0; j < 8; ++j)
            #pragma unroll
            for (int t = 0; t < 4; ++t) acc[i][j][t] = 0.f;

    auto load_stage = [&](int s, int k0) {
        {
            const __nv_bfloat16* gh = Ah + (size_t)(m0 + arow)*NF + k0 + acol;
            const __nv_bfloat16* gl = Al + (size_t)(m0 + arow)*NF + k0 + acol;
            uint32_t dh = smem_u32(sAh + s*SA_ + arow*40 + acol);
            uint32_t dl = smem_u32(sAl + s*SA_ + arow*40 + acol);
            cp16(dh, gh); cp16(dh+16, gh+8);
            cp16(dl, gl); cp16(dl+16, gl+8);
        }
        {
            const __nv_bfloat16* gh = Bh + (size_t)(k0 + brow)*NW + n0 + bcol;
            const __nv_bfloat16* gl = Bl + (size_t)(k0 + brow)*NW + n0 + bcol;
            uint32_t dh = smem_u32(sBh + s*SB_ + brow*136 + bcol);
            uint32_t dl = smem_u32(sBl + s*SB_ + brow*136 + bcol);
            cp16(dh, gh); cp16(dh+128, gh+64);
            cp16(dl, gl); cp16(dl+128, gl+64);
        }
    };

    load_stage(0, 0);  cp_commit();
    load_stage(1, 32); cp_commit();
    const int KT = NF/32;
    for (int kt = 0; kt < KT; ++kt) {
        if (kt + 1 < KT) cp_wait<1>(); else cp_wait<0>();
        __syncthreads();
        if (kt + 2 < KT) { load_stage((kt+2)%3, (kt+2)*32); cp_commit(); }
        int s = kt % 3;
        const __nv_bfloat16* cAh = sAh + s*SA_;
        const __nv_bfloat16* cAl = sAl + s*SA_;
        const __nv_bfloat16* cBh = sBh + s*SB_;
        const __nv_bfloat16* cBl = sBl + s*SB_;
        #pragma unroll
        for (int ks = 0; ks < 32; ks += 16) {
            uint32_t ahf[2][4], alf[2][4];
            #pragma unroll
            for (int mt = 0; mt < 2; ++mt) {
                int roff = (wm + mt*16 + (lane & 15))*40 + ks + ((lane >> 4) << 3);
                ldsm4(ahf[mt], smem_u32(cAh + roff));
                ldsm4(alf[mt], smem_u32(cAl + roff));
            }
            #pragma unroll
            for (int p = 0; p < 4; ++p) {
                uint32_t bhf[4], blf[4];
                int boff = (ks + (lane & 15))*136 + wn + p*16 + ((lane >> 4) << 3);
                ldsm4t(bhf, smem_u32(cBh + boff));
                ldsm4t(blf, smem_u32(cBl + boff));
                #pragma unroll
                for (int mt = 0; mt < 2; ++mt) {
                    mma16816(acc[mt][2*p],   ahf[mt], bhf[0], bhf[1]);
                    mma16816(acc[mt][2*p],   ahf[mt], blf[0], blf[1]);
                    mma16816(acc[mt][2*p],   alf[mt], bhf[0], bhf[1]);
                    mma16816(acc[mt][2*p+1], ahf[mt], bhf[2], bhf[3]);
                    mma16816(acc[mt][2*p+1], ahf[mt], blf[2], blf[3]);
                    mma16816(acc[mt][2*p+1], alf[mt], bhf[2], bhf[3]);
                }
            }
        }
    }

    size_t zoff = (size_t)z*NF*NW;
    if (bsel == 0 || bsel == 1) {
        // rotary fused: partner row value via shfl_xor(4) (rows differ in bit0 of lane>>2)
        __nv_bfloat16* Dh = (bsel == 0 ? g_qh : g_kh);
        __nv_bfloat16* Dl = (bsel == 0 ? g_ql : g_kl);
        const float KC = 13.287712379549449f / 128.0f;   // log2(10000)/128
        int rpar = (lane >> 2) & 1;    // row parity (wm, mt*16 are even multiples)
        #pragma unroll
        for (int mt = 0; mt < 2; ++mt)
            #pragma unroll
            for (int nt = 0; nt < 8; ++nt) {
                float v0 = acc[mt][nt][0], v1 = acc[mt][nt][1];
                float v2 = acc[mt][nt][2], v3 = acc[mt][nt][3];
                float p0 = __shfl_xor_sync(0xffffffffu, v0, 4);
                float p1 = __shfl_xor_sync(0xffffffffu, v1, 4);
                float p2 = __shfl_xor_sync(0xffffffffu, v2, 4);
                float p3 = __shfl_xor_sync(0xffffffffu, v3, 4);
                int r = m0 + wm + mt*16 + (lane >> 2);
                int c = n0 + wn + nt*8 + (lane & 3)*2;
                // frequency depends on head-dim pair index: rows r and r+8 DIFFER
                float invA = exp2f(-(float)( r      & 126) * KC);
                float invB = exp2f(-(float)((r + 8) & 126) * KC);
                float snA0, csA0, snA1, csA1, snB0, csB0, snB1, csB1;
                sincosf((float)c       * invA, &snA0, &csA0);
                sincosf((float)(c + 1) * invA, &snA1, &csA1);
                sincosf((float)c       * invB, &snB0, &csB0);
                sincosf((float)(c + 1) * invB, &snB1, &csB1);
                float o0, o1, o2, o3;
                if (rpar == 0) {   // even row: x1*cos - x2*sin
                    o0 = v0*csA0 - p0*snA0; o1 = v1*csA1 - p1*snA1;
                    o2 = v2*csB0 - p2*snB0; o3 = v3*csB1 - p3*snB1;
                } else {           // odd row: x2*cos + x1*sin
                    o0 = v0*csA0 + p0*snA0; o1 = v1*csA1 + p1*snA1;
                    o2 = v2*csB0 + p2*snB0; o3 = v3*csB1 + p3*snB1;
                }
                size_t a0 = zoff + (size_t)r*NW + c;
                size_t a1 = zoff + (size_t)(r+8)*NW + c;
                __nv_bfloat16 h0,l0,h1,l1;
                split_bf16(o0, h0, l0); split_bf16(o1, h1, l1);
                *(__nv_bfloat162*)&Dh[a0] = __nv_bfloat162(h0, h1);
                *(__nv_bfloat162*)&Dl[a0] = __nv_bfloat162(l0, l1);
                split_bf16(o2, h0, l0); split_bf16(o3, h1, l1);
                *(__nv_bfloat162*)&Dh[a1] = __nv_bfloat162(h0, h1);
                *(__nv_bfloat162*)&Dl[a1] = __nv_bfloat162(l0, l1);
            }
    } else if (bsel == 2) {
        // V: transpose through smem, write bf16 hi/lo to [head][w][d] (d contiguous)
        float* T = (float*)sm_;   // [128 w][pitch 132]
        __syncthreads();
        #pragma unroll
        for (int mt = 0; mt < 2; ++mt)
            #pragma unroll
            for (int nt = 0; nt < 8; ++nt) {
                int r = wm + mt*16 + (lane >> 2);       // d within head
                int c = wn + nt*8 + (lane & 3)*2;       // w within tile
                T[(c  )*132 + r    ] = acc[mt][nt][0];
                T[(c+1)*132 + r    ] = acc[mt][nt][1];
                T[(c  )*132 + r + 8] = acc[mt][nt][2];
                T[(c+1)*132 + r + 8] = acc[mt][nt][3];
            }
        __syncthreads();
        size_t vbase = (((size_t)z*NHEAD + blockIdx.y)*NW + n0) * NHD;
        #pragma unroll
        for (int i = 0; i < 8; ++i) {
            int u = tid + i*256;            // 0..2047
            int w = u >> 4, seg = (u & 15)*8;
            const float* src = T + w*132 + seg;
            __align__(16) __nv_bfloat16 hh[8], ll[8];
            #pragma unroll
            for (int j = 0; j < 8; ++j) split_bf16(src[j], hh[j], ll[j]);
            size_t o = vbase + (size_t)w*NHD + seg;
            *(uint4*)&g_vth[o] = *(const uint4*)hh;
            *(uint4*)&g_vtl[o] = *(const uint4*)ll;
        }
    } else {
        float* C = Cext + zoff;
        #pragma unroll
        for (int mt = 0; mt < 2; ++mt)
            #pragma unroll
            for (int nt = 0; nt < 8; ++nt) {
                int r = m0 + wm + mt*16 + (lane >> 2);
                int c = n0 + wn + nt*8 + (lane & 3)*2;
                *(float2*)&C[(size_t)r*NW + c]     = make_float2(acc[mt][nt][0], acc[mt][nt][1]);
                *(float2*)&C[(size_t)(r+8)*NW + c] = make_float2(acc[mt][nt][2], acc[mt][nt][3]);
            }
    }
}

// ---------------- QK^T logits via tensor cores: S = Q^T K / 32 + prev ----------------
__global__ void __launch_bounds__(256, 2) qk_mma(
    const float* __restrict__ prev, float* __restrict__ qkout)
{
    extern __shared__ __nv_bfloat16 sm_[];
    __nv_bfloat16* sAh = sm_;
    __nv_bfloat16* sAl = sAh + 2*SB_;
    __nv_bfloat16* sBh = sAl + 2*SB_;
    __nv_bfloat16* sBl = sBh + 2*SB_;

    int hz = blockIdx.z;
    int bc = hz >> 3, hd = hz & 7;
    size_t slab = ((size_t)bc*NF + hd*NHD)*NW;
    const __nv_bfloat16* QhG = g_qh + slab;
    const __nv_bfloat16* QlG = g_ql + slab;
    const __nv_bfloat16* KhG = g_kh + slab;
    const __nv_bfloat16* KlG = g_kl + slab;

    int m0 = blockIdx.y*128, n0 = blockIdx.x*128;
    int tid = threadIdx.x;
    int lane = tid & 31, wrp = tid >> 5;
    int wm = (wrp >> 1)*32, wn = (wrp & 1)*64;

    int lrow = tid >> 3, lcol = (tid & 7)*8;

    float acc[2][8][4];
    #pragma unroll
    for (int i = 0; i < 2; ++i)
        #pragma unroll
        for (int j = 0; j < 8; ++j)
            #pragma unroll
            for (int t = 0; t < 4; ++t) acc[i][j][t] = 0.f;

    auto load_stage = [&](int s, int k0) {
        size_t grow = (size_t)(k0 + lrow)*NW;
        {
            const __nv_bfloat16* gh = QhG + grow + m0 + lcol;
            const __nv_bfloat16* gl = QlG + grow + m0 + lcol;
            uint32_t dh = smem_u32(sAh + s*SB_ + lrow*136 + lcol);
            uint32_t dl = smem_u32(sAl + s*SB_ + lrow*136 + lcol);
            cp16(dh, gh); cp16(dh+128, gh+64);
            cp16(dl, gl); cp16(dl+128, gl+64);
        }
        {
            const __nv_bfloat16* gh = KhG + grow + n0 + lcol;
            const __nv_bfloat16* gl = KlG + grow + n0 + lcol;
            uint32_t dh = smem_u32(sBh + s*SB_ + lrow*136 + lcol);
            uint32_t dl = smem_u32(sBl + s*SB_ + lrow*136 + lcol);
            cp16(dh, gh); cp16(dh+128, gh+64);
            cp16(dl, gl); cp16(dl+128, gl+64);
        }
    };

    load_stage(0, 0);
    cp_commit();
    const int KT = NHD/32;   // 4
    for (int kt = 0; kt < KT; ++kt) {
        if (kt + 1 < KT) { load_stage((kt+1)&1, (kt+1)*32); cp_commit(); cp_wait<1>(); }
        else             { cp_wait<0>(); }
        __syncthreads();
        int s = kt & 1;
        const __nv_bfloat16* cAh = sAh + s*SB_;
        const __nv_bfloat16* cAl = sAl + s*SB_;
        const __nv_bfloat16* cBh = sBh + s*SB_;
        const __nv_bfloat16* cBl = sBl + s*SB_;
        #pragma unroll
        for (int ks = 0; ks < 32; ks += 16) {
            uint32_t ahf[2][4], alf[2][4];
            #pragma unroll
            for (int mt = 0; mt < 2; ++mt) {
                int off = (ks + (lane & 7) + ((lane >> 4) << 3))*136
                        + wm + mt*16 + (((lane >> 3) & 1) << 3);
                ldsm4t(ahf[mt], smem_u32(cAh + off));
                ldsm4t(alf[mt], smem_u32(cAl + off));
            }
            #pragma unroll
            for (int p = 0; p < 4; ++p) {
                uint32_t bhf[4], blf[4];
                int boff = (ks + (lane & 15))*136 + wn + p*16 + ((lane >> 4) << 3);
                ldsm4t(bhf, smem_u32(cBh + boff));
                ldsm4t(blf, smem_u32(cBl + boff));
                #pragma unroll
                for (int mt = 0; mt < 2; ++mt) {
                    mma16816(acc[mt][2*p],   ahf[mt], bhf[0], bhf[1]);
                    mma16816(acc[mt][2*p],   ahf[mt], blf[0], blf[1]);
                    mma16816(acc[mt][2*p],   alf[mt], bhf[0], bhf[1]);
                    mma16816(acc[mt][2*p+1], ahf[mt], bhf[2], bhf[3]);
                    mma16816(acc[mt][2*p+1], ahf[mt], blf[2], blf[3]);
                    mma16816(acc[mt][2*p+1], alf[mt], bhf[2], bhf[3]);
                }
            }
        }
        __syncthreads();
    }

    const float scale = 1.0f / 32.0f;   // 1/sqrt(F)
    size_t base = (size_t)hz * NW * NW;
    #pragma unroll
    for (int mt = 0; mt < 2; ++mt)
        #pragma unroll
        for (int nt = 0; nt < 8; ++nt) {
            int r = m0 + wm + mt*16 + (lane >> 2);
            int c = n0 + wn + nt*8 + (lane & 3)*2;
            size_t o0 = base + (size_t)r*NW + c;
            size_t o1 = base + (size_t)(r+8)*NW + c;
            float2 p0 = *(const float2*)&prev[o0];
            float2 p1 = *(const float2*)&prev[o1];
            *(float2*)&qkout[o0] = make_float2(acc[mt][nt][0]*scale + p0.x,
                                               acc[mt][nt][1]*scale + p0.y);
            *(float2*)&qkout[o1] = make_float2(acc[mt][nt][2]*scale + p1.x,
                                               acc[mt][nt][3]*scale + p1.y);
        }
}

// ---------------- softmax(S) @ V on tensor cores: 64 q-rows per CTA ----------------
// P chunked: 16 chunks x [64 rows][pitch 40]. V [kw][136] double-buffered cp.async.
#define PCH (64*40)       // one P chunk: 2560 elements
#define VBUF (32*136)     // one V buffer: 4352 elements
__global__ void __launch_bounds__(256) softmax_pv_mma(const float* __restrict__ qk)
{
    extern __shared__ __nv_bfloat16 pv_[];
    __nv_bfloat16* sPh = pv_;                 // 16*PCH
    __nv_bfloat16* sPl = sPh + 16*PCH;        // 16*PCH
    __nv_bfloat16* sV  = sPl + 16*PCH;        // 2 stages x (hi|lo) x VBUF
    __shared__ float linv[64];

    int hz  = blockIdx.y;
    int qt  = blockIdx.x;
    int bc  = hz >> 3, hd = hz & 7;
    int qw0 = qt * 64;
    size_t slab = ((size_t)bc*NF + hd*NHD)*NW;          // for output a
    size_t vtb  = (size_t)hz * NW * NHD;                // transposed V base
    const float* S = qk + ((size_t)hz * NW + qw0) * NW;

    int tid = threadIdx.x;
    int lane = tid & 31, wrp = tid >> 5;

    auto load_v = [&](int stage, int kw0) {
        __nv_bfloat16* bh = sV + stage*2*VBUF;
        #pragma unroll
        for (int rep = 0; rep < 2; ++rep) {
            int u  = tid + rep*256;         // 0..511
            int kw = u >> 4, seg = (u & 15)*8;
            size_t src = vtb + (size_t)(kw0 + kw)*NHD + seg;
            cp16(smem_u32(bh + kw*136 + seg),        g_vth + src);
            cp16(smem_u32(bh + VBUF + kw*136 + seg), g_vtl + src);
        }
    };
    load_v(0, 0);  cp_commit();
    load_v(1, 32); cp_commit();

    // softmax: warp w handles rows w*8 .. w*8+7; one global read, exp in regs
    #pragma unroll
    for (int j = 0; j < 8; ++j) {
        int row = wrp*8 + j;
        const float* Sr = S + (size_t)row*NW;
        float v[16];
        #pragma unroll
        for (int i = 0; i < 4; ++i)
            *(float4*)&v[i*4] = *(const float4*)&Sr[i*128 + lane*4];
        float m = v[0];
        #pragma unroll
        for (int i = 1; i < 16; ++i) m = fmaxf(m, v[i]);
        #pragma unroll
        for (int o = 16; o; o >>= 1) m = fmaxf(m, __shfl_xor_sync(0xffffffffu, m, o));
        float s = 0.f;
        #pragma unroll
        for (int i = 0; i < 16; ++i) { v[i] = __expf(v[i] - m); s += v[i]; }
        #pragma unroll
        for (int o = 16; o; o >>= 1) s += __shfl_xor_sync(0xffffffffu, s, o);
        if (lane == 0) linv[row] = 1.f / s;
        #pragma unroll
        for (int i = 0; i < 4; ++i) {
            int ch = i*4 + (lane >> 3);
            int kb = (lane & 7)*4;
            int base = ch*PCH + row*40 + kb;
            __nv_bfloat16 h0,l0,h1,l1,h2,l2,h3,l3;
            split_bf16(v[i*4+0], h0, l0); split_bf16(v[i*4+1], h1, l1);
            split_bf16(v[i*4+2], h2, l2); split_bf16(v[i*4+3], h3, l3);
            *(__nv_bfloat162*)&sPh[base]     = __nv_bfloat162(h0, h1);
            *(__nv_bfloat162*)&sPh[base + 2] = __nv_bfloat162(h2, h3);
            *(__nv_bfloat162*)&sPl[base]     = __nv_bfloat162(l0, l1);
            *(__nv_bfloat162*)&sPl[base + 2] = __nv_bfloat162(l2, l3);
        }
    }
    __syncthreads();

    // MMA: 8 warps, warp tile m16 x n64: wm in {0,16,32,48}, wn in {0,64}
    int wm = (wrp >> 1)*16;
    int wn = (wrp & 1)*64;
    float acc[8][4];
    #pragma unroll
    for (int f = 0; f < 8; ++f)
        #pragma unroll
        for (int t = 0; t < 4; ++t) acc[f][t] = 0.f;

    for (int c = 0; c < 16; ++c) {
        if (c == 15) cp_wait<0>(); else cp_wait<1>();
        __syncthreads();
        const __nv_bfloat16* cVh = sV + (c & 1)*2*VBUF;
        const __nv_bfloat16* cVl = cVh + VBUF;
        const __nv_bfloat16* cPh = sPh + c*PCH;
        const __nv_bfloat16* cPl = sPl + c*PCH;
        #pragma unroll
        for (int ks = 0; ks < 32; ks += 16) {
            uint32_t ah[4], al[4];
            int roff = (wm + (lane & 15))*40 + ks + ((lane >> 4) << 3);   // gemm A index
            ldsm4(ah, smem_u32(cPh + roff));
            ldsm4(al, smem_u32(cPl + roff));
            #pragma unroll
            for (int p = 0; p < 4; ++p) {
                uint32_t bh[4], bl[4];
                int boff = (ks + (lane & 15))*136 + wn + p*16 + ((lane >> 4) << 3);  // gemm B index
                ldsm4t(bh, smem_u32(cVh + boff));
                ldsm4t(bl, smem_u32(cVl + boff));
                #pragma unroll
                for (int nf = 0; nf < 2; ++nf) {
                    float* a = acc[p*2 + nf];
                    mma16816(a, ah, bh[2*nf], bh[2*nf+1]);
                    mma16816(a, ah, bl[2*nf], bl[2*nf+1]);
                    mma16816(a, al, bh[2*nf], bh[2*nf+1]);
                }
            }
        }
        __syncthreads();
        if (c + 2 < 16) { load_v(c & 1, (c+2)*32); cp_commit(); }
    }

    // epilogue: normalize, transpose via smem (reuse P region as [128 d][pitch 72]), write
    __nv_bfloat16* Ath = sPh;
    __nv_bfloat16* Atl = sPl;
    int r0 = wm + (lane >> 2);
    float l0v = linv[r0], l1v = linv[r0 + 8];
    #pragma unroll
    for (int p = 0; p < 4; ++p)
        #pragma unroll
        for (int nf = 0; nf < 2; ++nf) {
            const float* a = acc[p*2 + nf];
            int nb = wn + p*16 + nf*8 + (lane & 3)*2;
            __nv_bfloat16 h, l;
            split_bf16(a[0]*l0v, h, l); Ath[(nb  )*72 + r0  ] = h; Atl[(nb  )*72 + r0  ] = l;
            split_bf16(a[1]*l0v, h, l); Ath[(nb+1)*72 + r0  ] = h; Atl[(nb+1)*72 + r0  ] = l;
            split_bf16(a[2]*l1v, h, l); Ath[(nb  )*72 + r0+8] = h; Atl[(nb  )*72 + r0+8] = l;
            split_bf16(a[3]*l1v, h, l); Ath[(nb+1)*72 + r0+8] = h; Atl[(nb+1)*72 + r0+8] = l;
        }
    __syncthreads();

    #pragma unroll
    for (int rep = 0; rep < 8; ++rep) {
        int u   = tid + rep*256;       // 0..2047
        int sel = u >> 10;             // 0 = hi, 1 = lo
        int v   = u & 1023;
        int d   = v >> 3;
        int w8  = (v & 7) * 8;
        const __nv_bfloat16* src = (sel ? Atl : Ath) + d*72 + w8;
        __nv_bfloat16* dst = (sel ? g_al : g_ah) + slab + (size_t)d*NW + qw0 + w8;
        *(uint4*)dst = *(const uint4*)src;
    }
}

// ---------------- launch ----------------
extern "C" void kernel_launch(void* const* d_in, const int* in_sizes, int n_in,
                              void* d_out, int out_size)
{
    const float* x       = (const float*)d_in[0];
    const float* prevqk  = (const float*)d_in[1];
    const float* wq_conv = (const float*)d_in[2];
    const float* bq_conv = (const float*)d_in[3];
    const float* wq_lin  = (const float*)d_in[4];
    const float* wk_conv = (const float*)d_in[5];
    const float* bk_conv = (const float*)d_in[6];
    const float* wk_lin  = (const float*)d_in[7];
    const float* wv_conv = (const float*)d_in[8];
    const float* bv_conv = (const float*)d_in[9];
    const float* wv_lin  = (const float*)d_in[10];
    const float* wo_lin  = (const float*)d_in[11];
    float* out   = (float*)d_out;
    float* qkout = out + TENS;     // tuple output: (out, qk) concatenated

    int smGemm = (6*SA_ + 6*SB_) * 2;              // 113664 bytes (3 stages)
    int smQk   = (8*SB_) * 2;                      // 69632 bytes
    int smPv   = (2*16*PCH + 4*VBUF) * 2;          // 198656 bytes
    cudaFuncSetAttribute(gemm_mma, cudaFuncAttributeMaxDynamicSharedMemorySize, smGemm);
    cudaFuncSetAttribute(qk_mma,   cudaFuncAttributeMaxDynamicSharedMemorySize, smQk);
    cudaFuncSetAttribute(softmax_pv_mma, cudaFuncAttributeMaxDynamicSharedMemorySize, smPv);

    // 1) three convs fused -> bf16 hi/lo
    conv3_kernel<<<dim3(NW/32, NF/32, NB), 256>>>(
        x, wq_conv, bq_conv, wk_conv, bk_conv, wv_conv, bv_conv);

    // 2) weight conversion
    wconvert_kernel<<<(unsigned)((WSZ + 255)/256), 256>>>(wq_lin, wk_lin, wv_lin, wo_lin);

    // 3) mc_linear for q,k,v on tensor cores (q/k: rotary fused; v: transposed hi/lo)
    dim3 gg(NW/128, NF/128, NBC);
    gemm_mma<<<gg, 256, smGemm>>>(0, 0, nullptr);
    gemm_mma<<<gg, 256, smGemm>>>(1, 1, nullptr);
    gemm_mma<<<gg, 256, smGemm>>>(2, 2, nullptr);

    // 4) QK^T logits -> qk output region
    qk_mma<<<dim3(NW/128, NW/128, NBC*NHEAD), 256, smQk>>>(prevqk, qkout);

    // 5) softmax @ V on tensor cores -> a (bf16 hi/lo), 64 q-rows per CTA
    softmax_pv_mma<<<dim3(NW/64, NBC*NHEAD), 256, smPv>>>(qkout);

    // 6) output projection on tensor cores -> out region
    gemm_mma<<<gg, 256, smGemm>>>(3, 3, out);
}

// round 17
// speedup vs baseline: 1.3251x; 1.0118x over previous
#include <cuda_runtime.h>
#include <cuda_bf16.h>
#include <math.h>
#include <stdint.h>

#define NB 2
#define NC 8
#define NF 1024
#define NW 512
#define NHEAD 8
#define NHD 128
#define NBC (NB*NC)
#define TENS ((size_t)NB*NC*NF*NW)          // 8388608
#define WSZ  ((size_t)NC*NF*NF)             // 8388608 per weight tensor

// ---------------- scratch (static device globals; no runtime alloc) ----------------
__device__ __align__(16) __nv_bfloat16 g_cqh[TENS], g_cql[TENS];
__device__ __align__(16) __nv_bfloat16 g_ckh[TENS], g_ckl[TENS];
__device__ __align__(16) __nv_bfloat16 g_cvh[TENS], g_cvl[TENS];
__device__ __align__(16) __nv_bfloat16 g_qh[TENS], g_ql[TENS];
__device__ __align__(16) __nv_bfloat16 g_kh[TENS], g_kl[TENS];
__device__ __align__(16) __nv_bfloat16 g_vth[TENS], g_vtl[TENS];   // V transposed: [bc*8+h][w][d]
__device__ __align__(16) __nv_bfloat16 g_ah[TENS], g_al[TENS];
__device__ __align__(16) __nv_bfloat16 g_wh[4*WSZ], g_wl[4*WSZ];

// ---------------- helpers ----------------
__device__ __forceinline__ void split_bf16(float x, __nv_bfloat16& h, __nv_bfloat16& l) {
    h = __float2bfloat16(x);
    l = __float2bfloat16(x - __bfloat162float(h));
}
__device__ __forceinline__ uint32_t smem_u32(const void* p) {
    return (uint32_t)__cvta_generic_to_shared(p);
}
__device__ __forceinline__ void cp16(uint32_t dst, const void* src) {
    asm volatile("cp.async.cg.shared.global [%0], [%1], 16;" :: "r"(dst), "l"(src));
}
__device__ __forceinline__ void cp_commit() { asm volatile("cp.async.commit_group;"); }
template<int N> __device__ __forceinline__ void cp_wait() {
    asm volatile("cp.async.wait_group %0;" :: "n"(N));
}
__device__ __forceinline__ void ldsm4(uint32_t r[4], uint32_t addr) {
    asm volatile("ldmatrix.sync.aligned.m8n8.x4.shared.b16 {%0,%1,%2,%3},[%4];"
                 : "=r"(r[0]), "=r"(r[1]), "=r"(r[2]), "=r"(r[3]) : "r"(addr));
}
__device__ __forceinline__ void ldsm4t(uint32_t r[4], uint32_t addr) {
    asm volatile("ldmatrix.sync.aligned.m8n8.x4.trans.shared.b16 {%0,%1,%2,%3},[%4];"
                 : "=r"(r[0]), "=r"(r[1]), "=r"(r[2]), "=r"(r[3]) : "r"(addr));
}
__device__ __forceinline__ void mma16816(float c[4], const uint32_t a[4], uint32_t b0, uint32_t b1) {
    asm volatile("mma.sync.aligned.m16n8k16.row.col.f32.bf16.bf16.f32 "
                 "{%0,%1,%2,%3},{%4,%5,%6,%7},{%8,%9},{%0,%1,%2,%3};"
                 : "+f"(c[0]), "+f"(c[1]), "+f"(c[2]), "+f"(c[3])
                 : "r"(a[0]), "r"(a[1]), "r"(a[2]), "r"(a[3]), "r"(b0), "r"(b1));
}

// ---------------- fused 3x conv2d (3x3, pad 1, C=8 in/out) -> bf16 hi/lo ----------------
__global__ void __launch_bounds__(256) conv3_kernel(
    const float* __restrict__ x,
    const float* __restrict__ wq, const float* __restrict__ bq,
    const float* __restrict__ wk, const float* __restrict__ bk,
    const float* __restrict__ wv, const float* __restrict__ bv)
{
    __shared__ float xs[NC][34][36];
    __shared__ float ws[3*NC*NC*9];
    int tid = threadIdx.x;
    int bxo = blockIdx.x * 32;
    int byo = blockIdx.y * 32;
    int b   = blockIdx.z;

    for (int i = tid; i < NC*NC*9; i += 256) {
        ws[i]             = wq[i];
        ws[NC*NC*9 + i]   = wk[i];
        ws[2*NC*NC*9 + i] = wv[i];
    }
    for (int i = tid; i < NC*34*34; i += 256) {
        int ci = i / (34*34);
        int r  = (i / 34) % 34;
        int cl = i % 34;
        int gy = byo + r - 1, gx = bxo + cl - 1;
        float v = 0.f;
        if (gy >= 0 && gy < NF && gx >= 0 && gx < NW)
            v = x[(((size_t)b*NC + ci)*NF + gy)*NW + gx];
        xs[ci][r][cl] = v;
    }
    __syncthreads();

    #pragma unroll
    for (int p = 0; p < 4; ++p) {
        int pid = tid + p*256;
        int py = pid >> 5, px = pid & 31;
        float aq[NC], ak[NC], av[NC];
        #pragma unroll
        for (int co = 0; co < NC; ++co) { aq[co]=bq[co]; ak[co]=bk[co]; av[co]=bv[co]; }
        #pragma unroll
        for (int ci = 0; ci < NC; ++ci) {
            float w9[9];
            #pragma unroll
            for (int dy = 0; dy < 3; ++dy)
                #pragma unroll
                for (int dx = 0; dx < 3; ++dx)
                    w9[dy*3+dx] = xs[ci][py+dy][px+dx];
            #pragma unroll
            for (int co = 0; co < NC; ++co) {
                int wb = (co*NC + ci)*9;
                float sq=0.f, sk=0.f, sv=0.f;
                #pragma unroll
                for (int t = 0; t < 9; ++t) {
                    sq += w9[t]*ws[wb+t];
                    sk += w9[t]*ws[NC*NC*9 + wb+t];
                    sv += w9[t]*ws[2*NC*NC*9 + wb+t];
                }
                aq[co]+=sq; ak[co]+=sk; av[co]+=sv;
            }
        }
        int gy = byo + py, gx = bxo + px;
        #pragma unroll
        for (int co = 0; co < NC; ++co) {
            size_t o = (((size_t)b*NC+co)*NF + gy)*NW + gx;
            __nv_bfloat16 h, l;
            split_bf16(aq[co], h, l); g_cqh[o]=h; g_cql[o]=l;
            split_bf16(ak[co], h, l); g_ckh[o]=h; g_ckl[o]=l;
            split_bf16(av[co], h, l); g_cvh[o]=h; g_cvl[o]=l;
        }
    }
}

// ---------------- weight conversion: 4x (8,1024,1024) fp32 -> bf16 hi/lo ----------------
__global__ void __launch_bounds__(256) wconvert_kernel(
    const float* __restrict__ w0, const float* __restrict__ w1,
    const float* __restrict__ w2, const float* __restrict__ w3)
{
    size_t i = (size_t)blockIdx.x * blockDim.x + threadIdx.x;
    if (i >= WSZ) return;
    __nv_bfloat16 h, l;
    split_bf16(w0[i], h, l); g_wh[i]         = h; g_wl[i]         = l;
    split_bf16(w1[i], h, l); g_wh[WSZ + i]   = h; g_wl[WSZ + i]   = l;
    split_bf16(w2[i], h, l); g_wh[2*WSZ + i] = h; g_wl[2*WSZ + i] = l;
    split_bf16(w3[i], h, l); g_wh[3*WSZ + i] = h; g_wl[3*WSZ + i] = l;
}

// ---------------- mc_linear batched GEMM via bf16 tensor cores (3x split) ----------------
// C[z][m][n] = sum_k W[z%8][m][k] * B[z][k][n]; M=1024 N=512 K=1024
// CTA 128x128, BK=32, 3-stage cp.async pipeline, 8 warps, warp tile 32x64.
// bsel 0/1 (q/k): rotary fused in epilogue (pair exchange via shfl_xor 4), bf16 hi/lo out.
// bsel 2   (V)  : transposed bf16 hi/lo epilogue into [head][w][d] via smem.
// bsel 3   (out): plain fp32 write to Cext.
#define SA_ (128*40)
#define SB_ (32*136)
__global__ void __launch_bounds__(256, 2) gemm_mma(int wsel, int bsel, float* __restrict__ Cext)
{
    extern __shared__ __nv_bfloat16 sm_[];
    __nv_bfloat16* sAh = sm_;
    __nv_bfloat16* sAl = sAh + 3*SA_;
    __nv_bfloat16* sBh = sAl + 3*SA_;
    __nv_bfloat16* sBl = sBh + 3*SB_;

    int z = blockIdx.z;
    const __nv_bfloat16* Ah = g_wh + (size_t)wsel*WSZ + (size_t)(z & 7)*NF*NF;
    const __nv_bfloat16* Al = g_wl + (size_t)wsel*WSZ + (size_t)(z & 7)*NF*NF;
    const __nv_bfloat16 *BhG, *BlG;
    switch (bsel) {
        case 0:  BhG = g_cqh; BlG = g_cql; break;
        case 1:  BhG = g_ckh; BlG = g_ckl; break;
        case 2:  BhG = g_cvh; BlG = g_cvl; break;
        default: BhG = g_ah;  BlG = g_al;  break;
    }
    const __nv_bfloat16* Bh = BhG + (size_t)z*NF*NW;
    const __nv_bfloat16* Bl = BlG + (size_t)z*NF*NW;

    int m0 = blockIdx.y*128, n0 = blockIdx.x*128;
    int tid = threadIdx.x;
    int lane = tid & 31, wrp = tid >> 5;
    int wm = (wrp >> 1)*32, wn = (wrp & 1)*64;

    int arow = tid >> 1, acol = (tid & 1)*16;
    int brow = tid >> 3, bcol = (tid & 7)*8;

    float acc[2][8][4];
    #pragma unroll
    for (int i = 0; i < 2; ++i)
        #pragma unroll
        for (int j = 0; j < 8; ++j)
            #pragma unroll
            for (int t = 0; t < 4; ++t) acc[i][j][t] = 0.f;

    auto load_stage = [&](int s, int k0) {
        {
            const __nv_bfloat16* gh = Ah + (size_t)(m0 + arow)*NF + k0 + acol;
            const __nv_bfloat16* gl = Al + (size_t)(m0 + arow)*NF + k0 + acol;
            uint32_t dh = smem_u32(sAh + s*SA_ + arow*40 + acol);
            uint32_t dl = smem_u32(sAl + s*SA_ + arow*40 + acol);
            cp16(dh, gh); cp16(dh+16, gh+8);
            cp16(dl, gl); cp16(dl+16, gl+8);
        }
        {
            const __nv_bfloat16* gh = Bh + (size_t)(k0 + brow)*NW + n0 + bcol;
            const __nv_bfloat16* gl = Bl + (size_t)(k0 + brow)*NW + n0 + bcol;
            uint32_t dh = smem_u32(sBh + s*SB_ + brow*136 + bcol);
            uint32_t dl = smem_u32(sBl + s*SB_ + brow*136 + bcol);
            cp16(dh, gh); cp16(dh+128, gh+64);
            cp16(dl, gl); cp16(dl+128, gl+64);
        }
    };

    load_stage(0, 0);  cp_commit();
    load_stage(1, 32); cp_commit();
    const int KT = NF/32;
    for (int kt = 0; kt < KT; ++kt) {
        if (kt + 1 < KT) cp_wait<1>(); else cp_wait<0>();
        __syncthreads();
        if (kt + 2 < KT) { load_stage((kt+2)%3, (kt+2)*32); cp_commit(); }
        int s = kt % 3;
        const __nv_bfloat16* cAh = sAh + s*SA_;
        const __nv_bfloat16* cAl = sAl + s*SA_;
        const __nv_bfloat16* cBh = sBh + s*SB_;
        const __nv_bfloat16* cBl = sBl + s*SB_;
        #pragma unroll
        for (int ks = 0; ks < 32; ks += 16) {
            uint32_t ahf[2][4], alf[2][4];
            #pragma unroll
            for (int mt = 0; mt < 2; ++mt) {
                int roff = (wm + mt*16 + (lane & 15))*40 + ks + ((lane >> 4) << 3);
                ldsm4(ahf[mt], smem_u32(cAh + roff));
                ldsm4(alf[mt], smem_u32(cAl + roff));
            }
            #pragma unroll
            for (int p = 0; p < 4; ++p) {
                uint32_t bhf[4], blf[4];
                int boff = (ks + (lane & 15))*136 + wn + p*16 + ((lane >> 4) << 3);
                ldsm4t(bhf, smem_u32(cBh + boff));
                ldsm4t(blf, smem_u32(cBl + boff));
                #pragma unroll
                for (int mt = 0; mt < 2; ++mt) {
                    mma16816(acc[mt][2*p],   ahf[mt], bhf[0], bhf[1]);
                    mma16816(acc[mt][2*p],   ahf[mt], blf[0], blf[1]);
                    mma16816(acc[mt][2*p],   alf[mt], bhf[0], bhf[1]);
                    mma16816(acc[mt][2*p+1], ahf[mt], bhf[2], bhf[3]);
                    mma16816(acc[mt][2*p+1], ahf[mt], blf[2], blf[3]);
                    mma16816(acc[mt][2*p+1], alf[mt], bhf[2], bhf[3]);
                }
            }
        }
    }

    size_t zoff = (size_t)z*NF*NW;
    if (bsel == 0 || bsel == 1) {
        // rotary fused: partner row value via shfl_xor(4) (rows differ in bit0 of lane>>2)
        __nv_bfloat16* Dh = (bsel == 0 ? g_qh : g_kh);
        __nv_bfloat16* Dl = (bsel == 0 ? g_ql : g_kl);
        const float KC = 13.287712379549449f / 128.0f;   // log2(10000)/128
        int rpar = (lane >> 2) & 1;    // row parity (wm, mt*16 are even multiples)
        #pragma unroll
        for (int mt = 0; mt < 2; ++mt)
            #pragma unroll
            for (int nt = 0; nt < 8; ++nt) {
                float v0 = acc[mt][nt][0], v1 = acc[mt][nt][1];
                float v2 = acc[mt][nt][2], v3 = acc[mt][nt][3];
                float p0 = __shfl_xor_sync(0xffffffffu, v0, 4);
                float p1 = __shfl_xor_sync(0xffffffffu, v1, 4);
                float p2 = __shfl_xor_sync(0xffffffffu, v2, 4);
                float p3 = __shfl_xor_sync(0xffffffffu, v3, 4);
                int r = m0 + wm + mt*16 + (lane >> 2);
                int c = n0 + wn + nt*8 + (lane & 3)*2;
                // frequency depends on head-dim pair index: rows r and r+8 DIFFER
                float invA = exp2f(-(float)( r      & 126) * KC);
                float invB = exp2f(-(float)((r + 8) & 126) * KC);
                float snA0, csA0, snA1, csA1, snB0, csB0, snB1, csB1;
                sincosf((float)c       * invA, &snA0, &csA0);
                sincosf((float)(c + 1) * invA, &snA1, &csA1);
                sincosf((float)c       * invB, &snB0, &csB0);
                sincosf((float)(c + 1) * invB, &snB1, &csB1);
                float o0, o1, o2, o3;
                if (rpar == 0) {   // even row: x1*cos - x2*sin
                    o0 = v0*csA0 - p0*snA0; o1 = v1*csA1 - p1*snA1;
                    o2 = v2*csB0 - p2*snB0; o3 = v3*csB1 - p3*snB1;
                } else {           // odd row: x2*cos + x1*sin
                    o0 = v0*csA0 + p0*snA0; o1 = v1*csA1 + p1*snA1;
                    o2 = v2*csB0 + p2*snB0; o3 = v3*csB1 + p3*snB1;
                }
                size_t a0 = zoff + (size_t)r*NW + c;
                size_t a1 = zoff + (size_t)(r+8)*NW + c;
                __nv_bfloat16 h0,l0,h1,l1;
                split_bf16(o0, h0, l0); split_bf16(o1, h1, l1);
                *(__nv_bfloat162*)&Dh[a0] = __nv_bfloat162(h0, h1);
                *(__nv_bfloat162*)&Dl[a0] = __nv_bfloat162(l0, l1);
                split_bf16(o2, h0, l0); split_bf16(o3, h1, l1);
                *(__nv_bfloat162*)&Dh[a1] = __nv_bfloat162(h0, h1);
                *(__nv_bfloat162*)&Dl[a1] = __nv_bfloat162(l0, l1);
            }
    } else if (bsel == 2) {
        // V: transpose through smem, write bf16 hi/lo to [head][w][d] (d contiguous)
        float* T = (float*)sm_;   // [128 w][pitch 132]
        __syncthreads();
        #pragma unroll
        for (int mt = 0; mt < 2; ++mt)
            #pragma unroll
            for (int nt = 0; nt < 8; ++nt) {
                int r = wm + mt*16 + (lane >> 2);       // d within head
                int c = wn + nt*8 + (lane & 3)*2;       // w within tile
                T[(c  )*132 + r    ] = acc[mt][nt][0];
                T[(c+1)*132 + r    ] = acc[mt][nt][1];
                T[(c  )*132 + r + 8] = acc[mt][nt][2];
                T[(c+1)*132 + r + 8] = acc[mt][nt][3];
            }
        __syncthreads();
        size_t vbase = (((size_t)z*NHEAD + blockIdx.y)*NW + n0) * NHD;
        #pragma unroll
        for (int i = 0; i < 8; ++i) {
            int u = tid + i*256;            // 0..2047
            int w = u >> 4, seg = (u & 15)*8;
            const float* src = T + w*132 + seg;
            __align__(16) __nv_bfloat16 hh[8], ll[8];
            #pragma unroll
            for (int j = 0; j < 8; ++j) split_bf16(src[j], hh[j], ll[j]);
            size_t o = vbase + (size_t)w*NHD + seg;
            *(uint4*)&g_vth[o] = *(const uint4*)hh;
            *(uint4*)&g_vtl[o] = *(const uint4*)ll;
        }
    } else {
        float* C = Cext + zoff;
        #pragma unroll
        for (int mt = 0; mt < 2; ++mt)
            #pragma unroll
            for (int nt = 0; nt < 8; ++nt) {
                int r = m0 + wm + mt*16 + (lane >> 2);
                int c = n0 + wn + nt*8 + (lane & 3)*2;
                *(float2*)&C[(size_t)r*NW + c]     = make_float2(acc[mt][nt][0], acc[mt][nt][1]);
                *(float2*)&C[(size_t)(r+8)*NW + c] = make_float2(acc[mt][nt][2], acc[mt][nt][3]);
            }
    }
}

// ---------------- QK^T logits via tensor cores: S = Q^T K / 32 + prev ----------------
__global__ void __launch_bounds__(256, 2) qk_mma(
    const float* __restrict__ prev, float* __restrict__ qkout)
{
    extern __shared__ __nv_bfloat16 sm_[];
    __nv_bfloat16* sAh = sm_;
    __nv_bfloat16* sAl = sAh + 2*SB_;
    __nv_bfloat16* sBh = sAl + 2*SB_;
    __nv_bfloat16* sBl = sBh + 2*SB_;

    int hz = blockIdx.z;
    int bc = hz >> 3, hd = hz & 7;
    size_t slab = ((size_t)bc*NF + hd*NHD)*NW;
    const __nv_bfloat16* QhG = g_qh + slab;
    const __nv_bfloat16* QlG = g_ql + slab;
    const __nv_bfloat16* KhG = g_kh + slab;
    const __nv_bfloat16* KlG = g_kl + slab;

    int m0 = blockIdx.y*128, n0 = blockIdx.x*128;
    int tid = threadIdx.x;
    int lane = tid & 31, wrp = tid >> 5;
    int wm = (wrp >> 1)*32, wn = (wrp & 1)*64;

    int lrow = tid >> 3, lcol = (tid & 7)*8;

    float acc[2][8][4];
    #pragma unroll
    for (int i = 0; i < 2; ++i)
        #pragma unroll
        for (int j = 0; j < 8; ++j)
            #pragma unroll
            for (int t = 0; t < 4; ++t) acc[i][j][t] = 0.f;

    auto load_stage = [&](int s, int k0) {
        size_t grow = (size_t)(k0 + lrow)*NW;
        {
            const __nv_bfloat16* gh = QhG + grow + m0 + lcol;
            const __nv_bfloat16* gl = QlG + grow + m0 + lcol;
            uint32_t dh = smem_u32(sAh + s*SB_ + lrow*136 + lcol);
            uint32_t dl = smem_u32(sAl + s*SB_ + lrow*136 + lcol);
            cp16(dh, gh); cp16(dh+128, gh+64);
            cp16(dl, gl); cp16(dl+128, gl+64);
        }
        {
            const __nv_bfloat16* gh = KhG + grow + n0 + lcol;
            const __nv_bfloat16* gl = KlG + grow + n0 + lcol;
            uint32_t dh = smem_u32(sBh + s*SB_ + lrow*136 + lcol);
            uint32_t dl = smem_u32(sBl + s*SB_ + lrow*136 + lcol);
            cp16(dh, gh); cp16(dh+128, gh+64);
            cp16(dl, gl); cp16(dl+128, gl+64);
        }
    };

    load_stage(0, 0);
    cp_commit();
    const int KT = NHD/32;   // 4
    for (int kt = 0; kt < KT; ++kt) {
        if (kt + 1 < KT) { load_stage((kt+1)&1, (kt+1)*32); cp_commit(); cp_wait<1>(); }
        else             { cp_wait<0>(); }
        __syncthreads();
        int s = kt & 1;
        const __nv_bfloat16* cAh = sAh + s*SB_;
        const __nv_bfloat16* cAl = sAl + s*SB_;
        const __nv_bfloat16* cBh = sBh + s*SB_;
        const __nv_bfloat16* cBl = sBl + s*SB_;
        #pragma unroll
        for (int ks = 0; ks < 32; ks += 16) {
            uint32_t ahf[2][4], alf[2][4];
            #pragma unroll
            for (int mt = 0; mt < 2; ++mt) {
                int off = (ks + (lane & 7) + ((lane >> 4) << 3))*136
                        + wm + mt*16 + (((lane >> 3) & 1) << 3);
                ldsm4t(ahf[mt], smem_u32(cAh + off));
                ldsm4t(alf[mt], smem_u32(cAl + off));
            }
            #pragma unroll
            for (int p = 0; p < 4; ++p) {
                uint32_t bhf[4], blf[4];
                int boff = (ks + (lane & 15))*136 + wn + p*16 + ((lane >> 4) << 3);
                ldsm4t(bhf, smem_u32(cBh + boff));
                ldsm4t(blf, smem_u32(cBl + boff));
                #pragma unroll
                for (int mt = 0; mt < 2; ++mt) {
                    mma16816(acc[mt][2*p],   ahf[mt], bhf[0], bhf[1]);
                    mma16816(acc[mt][2*p],   ahf[mt], blf[0], blf[1]);
                    mma16816(acc[mt][2*p],   alf[mt], bhf[0], bhf[1]);
                    mma16816(acc[mt][2*p+1], ahf[mt], bhf[2], bhf[3]);
                    mma16816(acc[mt][2*p+1], ahf[mt], blf[2], blf[3]);
                    mma16816(acc[mt][2*p+1], alf[mt], bhf[2], bhf[3]);
                }
            }
        }
        __syncthreads();
    }

    const float scale = 1.0f / 32.0f;   // 1/sqrt(F)
    size_t base = (size_t)hz * NW * NW;
    #pragma unroll
    for (int mt = 0; mt < 2; ++mt)
        #pragma unroll
        for (int nt = 0; nt < 8; ++nt) {
            int r = m0 + wm + mt*16 + (lane >> 2);
            int c = n0 + wn + nt*8 + (lane & 3)*2;
            size_t o0 = base + (size_t)r*NW + c;
            size_t o1 = base + (size_t)(r+8)*NW + c;
            float2 p0 = *(const float2*)&prev[o0];
            float2 p1 = *(const float2*)&prev[o1];
            *(float2*)&qkout[o0] = make_float2(acc[mt][nt][0]*scale + p0.x,
                                               acc[mt][nt][1]*scale + p0.y);
            *(float2*)&qkout[o1] = make_float2(acc[mt][nt][2]*scale + p1.x,
                                               acc[mt][nt][3]*scale + p1.y);
        }
}

// ---------------- softmax(S) @ V on tensor cores: 64 q-rows, 512 threads (16 warps) -------
// P chunked: 16 chunks x [64 rows][pitch 40]. V [kw][136] double-buffered cp.async.
#define PCH (64*40)       // one P chunk: 2560 elements
#define VBUF (32*136)     // one V buffer: 4352 elements
__global__ void __launch_bounds__(512) softmax_pv_mma(const float* __restrict__ qk)
{
    extern __shared__ __nv_bfloat16 pv_[];
    __nv_bfloat16* sPh = pv_;                 // 16*PCH
    __nv_bfloat16* sPl = sPh + 16*PCH;        // 16*PCH
    __nv_bfloat16* sV  = sPl + 16*PCH;        // 2 stages x (hi|lo) x VBUF
    __shared__ float linv[64];

    int hz  = blockIdx.y;
    int qt  = blockIdx.x;
    int bc  = hz >> 3, hd = hz & 7;
    int qw0 = qt * 64;
    size_t slab = ((size_t)bc*NF + hd*NHD)*NW;          // for output a
    size_t vtb  = (size_t)hz * NW * NHD;                // transposed V base
    const float* S = qk + ((size_t)hz * NW + qw0) * NW;

    int tid = threadIdx.x;
    int lane = tid & 31, wrp = tid >> 5;    // 16 warps

    auto load_v = [&](int stage, int kw0) {
        __nv_bfloat16* bh = sV + stage*2*VBUF;
        int u  = tid;                       // 0..511
        int kw = u >> 4, seg = (u & 15)*8;
        size_t src = vtb + (size_t)(kw0 + kw)*NHD + seg;
        cp16(smem_u32(bh + kw*136 + seg),        g_vth + src);
        cp16(smem_u32(bh + VBUF + kw*136 + seg), g_vtl + src);
    };
    load_v(0, 0);  cp_commit();
    load_v(1, 32); cp_commit();

    // softmax: warp w handles rows w*4 .. w*4+3; one global read, exp in regs
    #pragma unroll
    for (int j = 0; j < 4; ++j) {
        int row = wrp*4 + j;
        const float* Sr = S + (size_t)row*NW;
        float v[16];
        #pragma unroll
        for (int i = 0; i < 4; ++i)
            *(float4*)&v[i*4] = *(const float4*)&Sr[i*128 + lane*4];
        float m = v[0];
        #pragma unroll
        for (int i = 1; i < 16; ++i) m = fmaxf(m, v[i]);
        #pragma unroll
        for (int o = 16; o; o >>= 1) m = fmaxf(m, __shfl_xor_sync(0xffffffffu, m, o));
        float s = 0.f;
        #pragma unroll
        for (int i = 0; i < 16; ++i) { v[i] = __expf(v[i] - m); s += v[i]; }
        #pragma unroll
        for (int o = 16; o; o >>= 1) s += __shfl_xor_sync(0xffffffffu, s, o);
        if (lane == 0) linv[row] = 1.f / s;
        #pragma unroll
        for (int i = 0; i < 4; ++i) {
            int ch = i*4 + (lane >> 3);
            int kb = (lane & 7)*4;
            int base = ch*PCH + row*40 + kb;
            __nv_bfloat16 h0,l0,h1,l1,h2,l2,h3,l3;
            split_bf16(v[i*4+0], h0, l0); split_bf16(v[i*4+1], h1, l1);
            split_bf16(v[i*4+2], h2, l2); split_bf16(v[i*4+3], h3, l3);
            *(__nv_bfloat162*)&sPh[base]     = __nv_bfloat162(h0, h1);
            *(__nv_bfloat162*)&sPh[base + 2] = __nv_bfloat162(h2, h3);
            *(__nv_bfloat162*)&sPl[base]     = __nv_bfloat162(l0, l1);
            *(__nv_bfloat162*)&sPl[base + 2] = __nv_bfloat162(l2, l3);
        }
    }
    __syncthreads();

    // MMA: 16 warps, warp tile m16 x n32: wm in {0,16,32,48}, wn in {0,32,64,96}
    int wm = (wrp >> 2)*16;
    int wn = (wrp & 3)*32;
    float acc[4][4];
    #pragma unroll
    for (int f = 0; f < 4; ++f)
        #pragma unroll
        for (int t = 0; t < 4; ++t) acc[f][t] = 0.f;

    for (int c = 0; c < 16; ++c) {
        if (c == 15) cp_wait<0>(); else cp_wait<1>();
        __syncthreads();
        const __nv_bfloat16* cVh = sV + (c & 1)*2*VBUF;
        const __nv_bfloat16* cVl = cVh + VBUF;
        const __nv_bfloat16* cPh = sPh + c*PCH;
        const __nv_bfloat16* cPl = sPl + c*PCH;
        #pragma unroll
        for (int ks = 0; ks < 32; ks += 16) {
            uint32_t ah[4], al[4];
            int roff = (wm + (lane & 15))*40 + ks + ((lane >> 4) << 3);   // gemm A index
            ldsm4(ah, smem_u32(cPh + roff));
            ldsm4(al, smem_u32(cPl + roff));
            #pragma unroll
            for (int p = 0; p < 2; ++p) {
                uint32_t bh[4], bl[4];
                int boff = (ks + (lane & 15))*136 + wn + p*16 + ((lane >> 4) << 3);  // gemm B index
                ldsm4t(bh, smem_u32(cVh + boff));
                ldsm4t(bl, smem_u32(cVl + boff));
                #pragma unroll
                for (int nf = 0; nf < 2; ++nf) {
                    float* a = acc[p*2 + nf];
                    mma16816(a, ah, bh[2*nf], bh[2*nf+1]);
                    mma16816(a, ah, bl[2*nf], bl[2*nf+1]);
                    mma16816(a, al, bh[2*nf], bh[2*nf+1]);
                }
            }
        }
        __syncthreads();
        if (c + 2 < 16) { load_v(c & 1, (c+2)*32); cp_commit(); }
    }

    // epilogue: normalize, transpose via smem (reuse P region as [128 d][pitch 72]), write
    __nv_bfloat16* Ath = sPh;
    __nv_bfloat16* Atl = sPl;
    int r0 = wm + (lane >> 2);
    float l0v = linv[r0], l1v = linv[r0 + 8];
    #pragma unroll
    for (int p = 0; p < 2; ++p)
        #pragma unroll
        for (int nf = 0; nf < 2; ++nf) {
            const float* a = acc[p*2 + nf];
            int nb = wn + p*16 + nf*8 + (lane & 3)*2;
            __nv_bfloat16 h, l;
            split_bf16(a[0]*l0v, h, l); Ath[(nb  )*72 + r0  ] = h; Atl[(nb  )*72 + r0  ] = l;
            split_bf16(a[1]*l0v, h, l); Ath[(nb+1)*72 + r0  ] = h; Atl[(nb+1)*72 + r0  ] = l;
            split_bf16(a[2]*l1v, h, l); Ath[(nb  )*72 + r0+8] = h; Atl[(nb  )*72 + r0+8] = l;
            split_bf16(a[3]*l1v, h, l); Ath[(nb+1)*72 + r0+8] = h; Atl[(nb+1)*72 + r0+8] = l;
        }
    __syncthreads();

    #pragma unroll
    for (int rep = 0; rep < 4; ++rep) {
        int u   = tid + rep*512;       // 0..2047
        int sel = u >> 10;             // 0 = hi, 1 = lo
        int v   = u & 1023;
        int d   = v >> 3;
        int w8  = (v & 7) * 8;
        const __nv_bfloat16* src = (sel ? Atl : Ath) + d*72 + w8;
        __nv_bfloat16* dst = (sel ? g_al : g_ah) + slab + (size_t)d*NW + qw0 + w8;
        *(uint4*)dst = *(const uint4*)src;
    }
}

// ---------------- launch ----------------
extern "C" void kernel_launch(void* const* d_in, const int* in_sizes, int n_in,
                              void* d_out, int out_size)
{
    const float* x       = (const float*)d_in[0];
    const float* prevqk  = (const float*)d_in[1];
    const float* wq_conv = (const float*)d_in[2];
    const float* bq_conv = (const float*)d_in[3];
    const float* wq_lin  = (const float*)d_in[4];
    const float* wk_conv = (const float*)d_in[5];
    const float* bk_conv = (const float*)d_in[6];
    const float* wk_lin  = (const float*)d_in[7];
    const float* wv_conv = (const float*)d_in[8];
    const float* bv_conv = (const float*)d_in[9];
    const float* wv_lin  = (const float*)d_in[10];
    const float* wo_lin  = (const float*)d_in[11];
    float* out   = (float*)d_out;
    float* qkout = out + TENS;     // tuple output: (out, qk) concatenated

    int smGemm = (6*SA_ + 6*SB_) * 2;              // 113664 bytes (3 stages)
    int smQk   = (8*SB_) * 2;                      // 69632 bytes
    int smPv   = (2*16*PCH + 4*VBUF) * 2;          // 198656 bytes
    cudaFuncSetAttribute(gemm_mma, cudaFuncAttributeMaxDynamicSharedMemorySize, smGemm);
    cudaFuncSetAttribute(qk_mma,   cudaFuncAttributeMaxDynamicSharedMemorySize, smQk);
    cudaFuncSetAttribute(softmax_pv_mma, cudaFuncAttributeMaxDynamicSharedMemorySize, smPv);

    // 1) three convs fused -> bf16 hi/lo
    conv3_kernel<<<dim3(NW/32, NF/32, NB), 256>>>(
        x, wq_conv, bq_conv, wk_conv, bk_conv, wv_conv, bv_conv);

    // 2) weight conversion
    wconvert_kernel<<<(unsigned)((WSZ + 255)/256), 256>>>(wq_lin, wk_lin, wv_lin, wo_lin);

    // 3) mc_linear for q,k,v on tensor cores (q/k: rotary fused; v: transposed hi/lo)
    dim3 gg(NW/128, NF/128, NBC);
    gemm_mma<<<gg, 256, smGemm>>>(0, 0, nullptr);
    gemm_mma<<<gg, 256, smGemm>>>(1, 1, nullptr);
    gemm_mma<<<gg, 256, smGemm>>>(2, 2, nullptr);

    // 4) QK^T logits -> qk output region
    qk_mma<<<dim3(NW/128, NW/128, NBC*NHEAD), 256, smQk>>>(prevqk, qkout);

    // 5) softmax @ V on tensor cores -> a (bf16 hi/lo), 64 q-rows, 512 threads
    softmax_pv_mma<<<dim3(NW/64, NBC*NHEAD), 512, smPv>>>(qkout);

    // 6) output projection on tensor cores -> out region
    gemm_mma<<<gg, 256, smGemm>>>(3, 3, out);
}